// round 11
// baseline (speedup 1.0000x reference)
#include <cuda_runtime.h>
#include <cuda_fp16.h>
#include <math.h>
#include <stdint.h>

#define T_LEN   1024
#define DMODEL  1024
#define QDIM    4096
#define HQ      64
#define HK      16
#define DH      64
#define SILU_SCALE 1.8137993642342178f   /* pi / sqrt(3) */
#define ATTN_SCALE 0.125f                /* DH^-0.5 */

static __device__ float  g_Q[T_LEN * QDIM];        // fp32 Q (pre-rope)
static __device__ float  g_K[T_LEN * DMODEL];      // fp32 K (pre-rope)
static __device__ __half g_Qh[T_LEN * QDIM];       // fp16 Q (post-rope)
static __device__ __half g_Kh[T_LEN * DMODEL];     // fp16 K (post-rope, prescaled)
static __device__ __half g_Vth[DMODEL * T_LEN];    // fp16 V^T: [d][t]
static __device__ __half g_OUTh[T_LEN * QDIM];     // fp16 attention output
static __device__ float  g_part[4 * T_LEN * DMODEL];
// fp16-converted GEMM operands (weights transposed to [N][K])
static __device__ __half g_Xh[T_LEN * DMODEL];
static __device__ __half g_WQt[QDIM * DMODEL];
static __device__ __half g_WKt[DMODEL * DMODEL];
static __device__ __half g_WVt[DMODEL * DMODEL];
static __device__ __half g_WOt[DMODEL * QDIM];

// ===========================================================================
// helpers
// ===========================================================================
__device__ __forceinline__ float f_ex2(float x) { float y; asm("ex2.approx.ftz.f32 %0,%1;" : "=f"(y) : "f"(x)); return y; }
__device__ __forceinline__ float f_lg2(float x) { float y; asm("lg2.approx.ftz.f32 %0,%1;" : "=f"(y) : "f"(x)); return y; }
__device__ __forceinline__ float f_rcp(float x) { float y; asm("rcp.approx.ftz.f32 %0,%1;" : "=f"(y) : "f"(x)); return y; }
__device__ __forceinline__ uint32_t smem_u32(const void* p) {
    uint32_t a;
    asm("{ .reg .u64 t; cvta.to.shared.u64 t, %1; cvt.u32.u64 %0, t; }" : "=r"(a) : "l"(p));
    return a;
}
__device__ __forceinline__ void cp_async16(uint32_t dst, const void* src) {
    asm volatile("cp.async.cg.shared.global [%0], [%1], 16;" :: "r"(dst), "l"(src));
}
#define CP_COMMIT() asm volatile("cp.async.commit_group;" ::: "memory")
#define CP_WAIT0()  asm volatile("cp.async.wait_group 0;"  ::: "memory")
#define CP_WAIT1()  asm volatile("cp.async.wait_group 1;"  ::: "memory")

__device__ __forceinline__ void mma_f16(float* d, const uint32_t* a, const uint32_t* b) {
    asm volatile(
        "mma.sync.aligned.m16n8k16.row.col.f32.f16.f16.f32 "
        "{%0,%1,%2,%3}, {%4,%5,%6,%7}, {%8,%9}, {%0,%1,%2,%3};"
        : "+f"(d[0]), "+f"(d[1]), "+f"(d[2]), "+f"(d[3])
        : "r"(a[0]), "r"(a[1]), "r"(a[2]), "r"(a[3]), "r"(b[0]), "r"(b[1]));
}
__device__ __forceinline__ uint32_t pack_h2(float a, float b) {
    __half2 h = __float22half2_rn(make_float2(a, b));
    return *(uint32_t*)&h;
}

// ---------------------------------------------------------------------------
// Convert X to fp16 (z=0) and transpose-convert weights to fp16 [N][K] (z>=1)
// ---------------------------------------------------------------------------
__global__ __launch_bounds__(256)
void convert_ops(const float* __restrict__ X, const float* __restrict__ WQ,
                 const float* __restrict__ WK, const float* __restrict__ WV,
                 const float* __restrict__ WO)
{
    int z = blockIdx.y;
    int tid = threadIdx.x;

    if (z == 0) {
        int i = blockIdx.x * 256 + tid;
        if (i < (T_LEN * DMODEL) / 4) {
            float4 v = ((const float4*)X)[i];
            uint2 o = { pack_h2(v.x, v.y), pack_h2(v.z, v.w) };
            ((uint2*)g_Xh)[i] = o;
        }
        return;
    }

    const float* src; __half* dst; int Kd, Nd;
    switch (z) {
        case 1:  src = WQ; dst = g_WQt; Kd = DMODEL; Nd = QDIM;   break;
        case 2:  src = WK; dst = g_WKt; Kd = DMODEL; Nd = DMODEL; break;
        case 3:  src = WV; dst = g_WVt; Kd = DMODEL; Nd = DMODEL; break;
        default: src = WO; dst = g_WOt; Kd = QDIM;   Nd = DMODEL; break;
    }
    int ntx = Nd >> 5;
    int tiles = ntx * (Kd >> 5);
    int bx = blockIdx.x;
    if (bx >= tiles) return;
    int tx = bx % ntx, ty = bx / ntx;

    __shared__ __half tile[32][33];
    int r = tid >> 5, c = tid & 31;
#pragma unroll
    for (int i = 0; i < 4; ++i) {
        int row = r + i * 8;
        tile[row][c] = __float2half(src[(size_t)(ty * 32 + row) * Nd + tx * 32 + c]);
    }
    __syncthreads();
#pragma unroll
    for (int i = 0; i < 4; ++i) {
        int row = r + i * 8;
        dst[(size_t)(tx * 32 + row) * Kd + ty * 32 + c] = tile[c][row];
    }
}

// ===========================================================================
// fp16 cp.async 3-stage pipelined GEMM (unchanged from R10)
// ===========================================================================
#define FP_PITCH 20
#define FP_TILE_WORDS (128 * FP_PITCH)
#define NSTAGE 3
#define FP_STG_WORDS (2 * FP_TILE_WORDS)
#define GEMM_SMEM_BYTES (NSTAGE * FP_STG_WORDS * 4)

template <bool BIAS, int OUTK>
__device__ __forceinline__ void gemm_body(
    const __half* __restrict__ A, const __half* __restrict__ Bt,
    const float* __restrict__ bias, float* __restrict__ C, __half* __restrict__ Ch,
    int lda, int ldb, int N, int m0, int n0, int kbase, int kLen)
{
    extern __shared__ uint32_t sm[];
    int tid  = threadIdx.x;
    int lane = tid & 31, wid = tid >> 5;
    int wm = wid & 3, wn = wid >> 2;
    int g = lane >> 2, tg = lane & 3;

    int crow = tid >> 1, cch = tid & 1;

    const __half* Abase = &A[(size_t)(m0 + crow) * lda + kbase + cch * 8];
    const __half* Bbase = &Bt[(size_t)(n0 + crow) * ldb + kbase + cch * 8];

    uint32_t aDst[NSTAGE], bDst[NSTAGE];
#pragma unroll
    for (int s = 0; s < NSTAGE; ++s) {
        aDst[s] = smem_u32(&sm[s * FP_STG_WORDS + crow * FP_PITCH + cch * 4]);
        bDst[s] = smem_u32(&sm[s * FP_STG_WORDS + FP_TILE_WORDS + crow * FP_PITCH + cch * 4]);
    }

#define ISSUE(it_)                                                \
    do {                                                          \
        int s_ = (it_) % NSTAGE;                                  \
        cp_async16(aDst[s_],      Abase + (it_) * 32);            \
        cp_async16(aDst[s_] + 32, Abase + (it_) * 32 + 16);       \
        cp_async16(bDst[s_],      Bbase + (it_) * 32);            \
        cp_async16(bDst[s_] + 32, Bbase + (it_) * 32 + 16);       \
        CP_COMMIT();                                              \
    } while (0)

    float acc[2][8][4];
#pragma unroll
    for (int mf = 0; mf < 2; ++mf)
#pragma unroll
        for (int nf = 0; nf < 8; ++nf)
#pragma unroll
            for (int q = 0; q < 4; ++q) acc[mf][nf][q] = 0.f;

    int NIT = kLen / 32;
    ISSUE(0);
    if (NIT > 1) ISSUE(1);

    for (int it = 0; it < NIT; ++it) {
        int s = it % NSTAGE;
        CP_WAIT1();
        __syncthreads();
        if (it + 2 < NIT) ISSUE(it + 2);

        const uint32_t* As = sm + s * FP_STG_WORDS;
        const uint32_t* Bs = As + FP_TILE_WORDS;
#pragma unroll
        for (int kk = 0; kk < 2; ++kk) {
            uint32_t af[2][4], bf[8][2];
#pragma unroll
            for (int mf = 0; mf < 2; ++mf) {
                const uint32_t* p = &As[(wm * 32 + mf * 16 + g) * FP_PITCH + kk * 8 + tg];
                af[mf][0] = p[0];
                af[mf][1] = p[8 * FP_PITCH];
                af[mf][2] = p[4];
                af[mf][3] = p[8 * FP_PITCH + 4];
            }
#pragma unroll
            for (int nf = 0; nf < 8; ++nf) {
                const uint32_t* p = &Bs[(wn * 64 + nf * 8 + g) * FP_PITCH + kk * 8 + tg];
                bf[nf][0] = p[0];
                bf[nf][1] = p[4];
            }
#pragma unroll
            for (int mf = 0; mf < 2; ++mf)
#pragma unroll
                for (int nf = 0; nf < 8; ++nf)
                    mma_f16(acc[mf][nf], af[mf], bf[nf]);
        }
        __syncthreads();
    }
#undef ISSUE

#pragma unroll
    for (int mf = 0; mf < 2; ++mf) {
        int r0 = m0 + wm * 32 + mf * 16 + g;
#pragma unroll
        for (int nf = 0; nf < 8; ++nf) {
            int c = n0 + wn * 64 + nf * 8 + 2 * tg;
            float b0 = 0.f, b1 = 0.f;
            if (BIAS) { b0 = bias[c]; b1 = bias[c + 1]; }
            if (OUTK == 1) {
                Ch[(size_t)c * T_LEN + r0]           = __float2half(acc[mf][nf][0] + b0);
                Ch[(size_t)(c + 1) * T_LEN + r0]     = __float2half(acc[mf][nf][1] + b1);
                Ch[(size_t)c * T_LEN + r0 + 8]       = __float2half(acc[mf][nf][2] + b0);
                Ch[(size_t)(c + 1) * T_LEN + r0 + 8] = __float2half(acc[mf][nf][3] + b1);
            } else {
                float2 v0 = { acc[mf][nf][0] + b0, acc[mf][nf][1] + b1 };
                float2 v1 = { acc[mf][nf][2] + b0, acc[mf][nf][3] + b1 };
                *(float2*)&C[(size_t)r0 * N + c]       = v0;
                *(float2*)&C[(size_t)(r0 + 8) * N + c] = v1;
            }
        }
    }
}

__global__ __launch_bounds__(256, 2)
void gemm_qkv(const float* __restrict__ b_Q, const float* __restrict__ b_K,
              const float* __restrict__ b_V,
              float* __restrict__ Qo, float* __restrict__ Ko)
{
    int bx = blockIdx.x, m0 = blockIdx.y * 128;
    if (bx < 32)
        gemm_body<true, 0>(g_Xh, g_WQt, b_Q, Qo, nullptr, DMODEL, DMODEL, QDIM, m0, bx * 128, 0, DMODEL);
    else if (bx < 40)
        gemm_body<true, 0>(g_Xh, g_WKt, b_K, Ko, nullptr, DMODEL, DMODEL, DMODEL, m0, (bx - 32) * 128, 0, DMODEL);
    else
        gemm_body<true, 1>(g_Xh, g_WVt, b_V, nullptr, g_Vth, DMODEL, DMODEL, DMODEL, m0, (bx - 40) * 128, 0, DMODEL);
}

__global__ __launch_bounds__(256, 2)
void gemm_tc_splitk(float* __restrict__ Cpart, int kPer)
{
    int z = blockIdx.z;
    gemm_body<false, 0>(g_OUTh, g_WOt, nullptr, Cpart + (size_t)z * T_LEN * DMODEL, nullptr,
                        QDIM, QDIM, DMODEL, blockIdx.y * 128, blockIdx.x * 128, z * kPer, kPer);
}

// ---------------------------------------------------------------------------
// RoPE + key_self/ATTN_SCALE folding; emits fp16 Q and K for attention.
// ---------------------------------------------------------------------------
__global__ __launch_bounds__(256)
void rope_kernel()
{
    int gw   = blockIdx.x * 8 + (threadIdx.x >> 5);
    int lane = threadIdx.x & 31;
    int slot = gw % (HQ + HK);
    int t    = gw / (HQ + HK);

    bool isK = (slot >= HQ);
    const float* ptr = isK ? (g_K + (size_t)t * DMODEL + (slot - HQ) * DH)
                           : (g_Q + (size_t)t * QDIM + slot * DH);
    __half* hptr = isK ? (g_Kh + (size_t)t * DMODEL + (slot - HQ) * DH)
                       : (g_Qh + (size_t)t * QDIM + slot * DH);

    float x1 = ptr[2 * lane];
    float x2 = ptr[2 * lane + 1];

    float inv = 1.0f / powf(10000.0f, (float)(2 * lane) / 64.0f);
    float fr  = (float)t * inv;
    float s, c;
    sincosf(fr, &s, &c);

    float o1 = x1 * c - x2 * s;
    float o2 = x1 * s + x2 * c;

    if (isK) {
        float nrm = x1 * x1 + x2 * x2;
#pragma unroll
        for (int off = 16; off; off >>= 1)
            nrm += __shfl_xor_sync(0xffffffffu, nrm, off);
        float ks  = fmaxf(nrm, 1e-6f);
        float scl = ATTN_SCALE * rsqrtf(ks);
        o1 *= scl;
        o2 *= scl;
    }
    hptr[lane]      = __float2half(o1);
    hptr[lane + 32] = __float2half(o2);
}

// ===========================================================================
// fp16 tensor-core attention v5: 128-query tiles. One block = (head, 128 q).
// 8 warps (4m x 2n); each warp: 32 q-rows x 32 cols. Q frags straight from
// gmem to registers. K/Vt cp.async double-buffered; 2 syncs/iter.
// ===========================================================================
#define HPITCH 36
#define HTILE_W (64 * HPITCH)
#define WS_WORDS (128 * HPITCH)
#define ATTN_SMEM_WORDS (4 * HTILE_W + WS_WORDS + 256 + 128)
#define ATTN_SMEM_BYTES (ATTN_SMEM_WORDS * 4)

__global__ __launch_bounds__(256, 2)
void attn_tc_kernel(const float* __restrict__ sinks, const float* __restrict__ v_nulls)
{
    extern __shared__ uint32_t smu[];
    uint32_t* KsB[2]  = { smu,               smu + HTILE_W };
    uint32_t* VtsB[2] = { smu + 2 * HTILE_W, smu + 3 * HTILE_W };
    uint32_t* Ws      = smu + 4 * HTILE_W;                 // 128 x HPITCH
    float* RSm = (float*)(smu + 4 * HTILE_W + WS_WORDS);   // [8][32]
    float* Tot = RSm + 256;                                // [128]

    int head = blockIdx.y;
    int qt   = (gridDim.x - 1) - blockIdx.x;   // heavy tiles first
    int kvh  = head & (HK - 1);
    int tid  = threadIdx.x;
    int lane = tid & 31, wid = tid >> 5;
    int wm = wid & 3, wn = wid >> 2;
    int g = lane >> 2, tg = lane & 3;
    float sink = sinks[head];
    int ktmax = 2 * qt + 1;

    // cp.async copy slots (64-row tiles)
    int crow = tid >> 3, cc = tid & 7;
    uint32_t ksA[2], vtA[2];
#pragma unroll
    for (int b = 0; b < 2; ++b) {
        ksA[b] = smem_u32(&KsB[b][crow * HPITCH + cc * 4]);
        vtA[b] = smem_u32(&VtsB[b][crow * HPITCH + cc * 4]);
    }
    const __half* kSrc  = g_Kh + (size_t)crow * DMODEL + kvh * DH + cc * 8;
    const __half* vtSrc = g_Vth + (size_t)(kvh * DH + crow) * T_LEN + cc * 8;

#define ISSUE_TILES(kt_, b_)                                                     \
    do {                                                                         \
        cp_async16(ksA[b_],                     kSrc + (size_t)(kt_) * 64 * DMODEL); \
        cp_async16(ksA[b_] + 32 * HPITCH * 4,   kSrc + (size_t)((kt_) * 64 + 32) * DMODEL); \
        cp_async16(vtA[b_],                     vtSrc + (kt_) * 64);             \
        cp_async16(vtA[b_] + 32 * HPITCH * 4,   vtSrc + 32 * T_LEN + (kt_) * 64); \
        CP_COMMIT();                                                             \
    } while (0)

    ISSUE_TILES(0, 0);

    // ---- Q A-fragments: direct gmem -> registers (k-contiguous fp16)
    int li0 = wm * 32 + g;                 // local row base (warp covers 32 rows)
    uint32_t afq[2][4][4];
#pragma unroll
    for (int mf = 0; mf < 2; ++mf) {
        int row0 = qt * 128 + li0 + mf * 16;
        const uint32_t* q0 = (const uint32_t*)(g_Qh + (size_t)row0 * QDIM + head * DH);
        const uint32_t* q1 = (const uint32_t*)(g_Qh + (size_t)(row0 + 8) * QDIM + head * DH);
#pragma unroll
        for (int kk = 0; kk < 4; ++kk) {
            afq[mf][kk][0] = q0[kk * 8 + tg];
            afq[mf][kk][1] = q1[kk * 8 + tg];
            afq[mf][kk][2] = q0[kk * 8 + 4 + tg];
            afq[mf][kk][3] = q1[kk * 8 + 4 + tg];
        }
    }

    float oacc[2][4][4];
#pragma unroll
    for (int mf = 0; mf < 2; ++mf)
#pragma unroll
        for (int nf = 0; nf < 4; ++nf)
#pragma unroll
            for (int q = 0; q < 4; ++q) oacc[mf][nf][q] = 0.f;
    float rs[2][2] = {{0.f, 0.f}, {0.f, 0.f}};
    int gi0 = qt * 128 + li0;

    for (int kt = 0; kt <= ktmax; ++kt) {
        int b = kt & 1;
        CP_WAIT0();
        __syncthreads();   // K[b]/Vt[b] ready; WV(kt-1) complete

        if (kt < ktmax) ISSUE_TILES(kt + 1, b ^ 1);

        const uint32_t* Ks  = KsB[b];
        const uint32_t* Vts = VtsB[b];

        // ---- S = Q @ K^T (2 m-frag groups x 4 n-frags x 4 kk = 32 HMMA)
        float sacc[2][4][4];
#pragma unroll
        for (int mf = 0; mf < 2; ++mf)
#pragma unroll
            for (int nf = 0; nf < 4; ++nf)
#pragma unroll
                for (int q = 0; q < 4; ++q) sacc[mf][nf][q] = 0.f;

#pragma unroll
        for (int kk = 0; kk < 4; ++kk) {
            uint32_t bf[4][2];
#pragma unroll
            for (int nf = 0; nf < 4; ++nf) {
                const uint32_t* bp = &Ks[(wn * 32 + nf * 8 + g) * HPITCH + kk * 8 + tg];
                bf[nf][0] = bp[0]; bf[nf][1] = bp[4];
            }
#pragma unroll
            for (int mf = 0; mf < 2; ++mf)
#pragma unroll
                for (int nf = 0; nf < 4; ++nf)
                    mma_f16(sacc[mf][nf], afq[mf][kk], bf[nf]);
        }

        // ---- activation in registers -> Ws (fp16 pairs)
        bool docausal = (kt >= 2 * qt);
#pragma unroll
        for (int mf = 0; mf < 2; ++mf) {
            int rloc = li0 + mf * 16;
#pragma unroll
            for (int nf = 0; nf < 4; ++nf) {
                int ljc = wn * 32 + nf * 8 + 2 * tg;
                int gj  = kt * 64 + ljc;
                float w[4];
#pragma unroll
                for (int q = 0; q < 4; ++q) {
                    float x = fminf(sacc[mf][nf][q], 60.f);
                    float t = f_ex2(x * 1.44269504f);
                    float u = f_lg2(1.0f + t);
                    float ww = 0.69314718f * u * f_rcp(1.0f + f_ex2(-SILU_SCALE * u));
                    int gi = gi0 + mf * 16 + ((q >> 1) << 3);
                    int gjj = gj + (q & 1);
                    if ((docausal && gjj > gi) || ww < sink) ww = 0.f;
                    w[q] = ww;
                }
                rs[mf][0] += w[0] + w[1];
                rs[mf][1] += w[2] + w[3];
                int wc = wn * 16 + nf * 4 + tg;
                Ws[rloc * HPITCH + wc]       = pack_h2(w[0], w[1]);
                Ws[(rloc + 8) * HPITCH + wc] = pack_h2(w[2], w[3]);
            }
        }
        __syncthreads();   // Ws visible

        // ---- O += W @ V (32 HMMA)
#pragma unroll
        for (int kk = 0; kk < 4; ++kk) {
            uint32_t af[2][4], bf[4][2];
#pragma unroll
            for (int mf = 0; mf < 2; ++mf) {
                const uint32_t* ap = &Ws[(li0 + mf * 16) * HPITCH + kk * 8 + tg];
                af[mf][0] = ap[0];
                af[mf][1] = ap[8 * HPITCH];
                af[mf][2] = ap[4];
                af[mf][3] = ap[8 * HPITCH + 4];
            }
#pragma unroll
            for (int nf = 0; nf < 4; ++nf) {
                const uint32_t* bp = &Vts[(wn * 32 + nf * 8 + g) * HPITCH + kk * 8 + tg];
                bf[nf][0] = bp[0]; bf[nf][1] = bp[4];
            }
#pragma unroll
            for (int mf = 0; mf < 2; ++mf)
#pragma unroll
                for (int nf = 0; nf < 4; ++nf)
                    mma_f16(oacc[mf][nf], af[mf], bf[nf]);
        }
    }
#undef ISSUE_TILES

    // ---- row-sum reduction: RSm[wid][32] rows of this warp
    __syncthreads();
#pragma unroll
    for (int mf = 0; mf < 2; ++mf)
#pragma unroll
        for (int rg = 0; rg < 2; ++rg) {
            float v = rs[mf][rg];
            v += __shfl_xor_sync(0xffffffffu, v, 1);
            v += __shfl_xor_sync(0xffffffffu, v, 2);
            if (tg == 0) RSm[wid * 32 + mf * 16 + rg * 8 + g] = v;
        }
    __syncthreads();
    if (tid < 128) {
        int wmm = tid >> 5, rl = tid & 31;
        Tot[tid] = RSm[wmm * 32 + rl] + RSm[(wmm + 4) * 32 + rl] + sink + 1e-6f;
    }
    __syncthreads();

    // ---- epilogue -> fp16 OUT
#pragma unroll
    for (int mf = 0; mf < 2; ++mf) {
        int rloc = li0 + mf * 16;
        float invT0 = 1.0f / Tot[rloc];
        float invT1 = 1.0f / Tot[rloc + 8];
        int grow = qt * 128 + rloc;
#pragma unroll
        for (int nf = 0; nf < 4; ++nf) {
            int dloc = wn * 32 + nf * 8 + 2 * tg;
            float vn0 = v_nulls[head * DH + dloc];
            float vn1 = v_nulls[head * DH + dloc + 1];
            uint32_t o0 = pack_h2((oacc[mf][nf][0] + sink * vn0) * invT0,
                                  (oacc[mf][nf][1] + sink * vn1) * invT0);
            uint32_t o1 = pack_h2((oacc[mf][nf][2] + sink * vn0) * invT1,
                                  (oacc[mf][nf][3] + sink * vn1) * invT1);
            *(uint32_t*)&g_OUTh[(size_t)grow * QDIM + head * DH + dloc]       = o0;
            *(uint32_t*)&g_OUTh[(size_t)(grow + 8) * QDIM + head * DH + dloc] = o1;
        }
    }
}

// ---------------------------------------------------------------------------
// Final reduce: Y = 0.25 * (sum of 4 K-split partials + sum_br bias)
// ---------------------------------------------------------------------------
__global__ __launch_bounds__(256)
void reduce_out_kernel(const float* __restrict__ part, const float* __restrict__ wob,
                       float* __restrict__ out)
{
    int idx = blockIdx.x * 256 + threadIdx.x;
    int d = idx & (DMODEL - 1);
    float s = part[idx] + part[idx + 1048576] + part[idx + 2097152] + part[idx + 3145728];
    float b = wob[d] + wob[DMODEL + d] + wob[2 * DMODEL + d] + wob[3 * DMODEL + d];
    out[idx] = 0.25f * (s + b);
}

// ---------------------------------------------------------------------------
extern "C" void kernel_launch(void* const* d_in, const int* in_sizes, int n_in,
                              void* d_out, int out_size)
{
    const float* X        = (const float*)d_in[0];
    const float* W_Q      = (const float*)d_in[1];
    const float* b_Q      = (const float*)d_in[2];
    const float* W_K      = (const float*)d_in[3];
    const float* b_K      = (const float*)d_in[4];
    const float* W_V      = (const float*)d_in[5];
    const float* b_V      = (const float*)d_in[6];
    const float* sinks    = (const float*)d_in[7];
    const float* v_nulls  = (const float*)d_in[8];
    const float* W_O      = (const float*)d_in[9];
    const float* W_O_bias = (const float*)d_in[10];
    float* out = (float*)d_out;

    float *Qp, *Kp, *PARTp;
    cudaGetSymbolAddress((void**)&Qp,    g_Q);
    cudaGetSymbolAddress((void**)&Kp,    g_K);
    cudaGetSymbolAddress((void**)&PARTp, g_part);

    cudaFuncSetAttribute(gemm_qkv, cudaFuncAttributeMaxDynamicSharedMemorySize, GEMM_SMEM_BYTES);
    cudaFuncSetAttribute(gemm_tc_splitk, cudaFuncAttributeMaxDynamicSharedMemorySize, GEMM_SMEM_BYTES);
    cudaFuncSetAttribute(attn_tc_kernel, cudaFuncAttributeMaxDynamicSharedMemorySize, ATTN_SMEM_BYTES);

    // fp16 conversion: X elementwise (z=0), weights transposed (z=1..4)
    convert_ops<<<dim3(4096, 5), 256>>>(X, W_Q, W_K, W_V, W_O);
    // fused Q/K/V projections (fp16 tensor cores; V written transposed fp16)
    gemm_qkv<<<dim3(48, 8, 1), 256, GEMM_SMEM_BYTES>>>(b_Q, b_K, b_V, Qp, Kp);
    // RoPE + key_self folding -> fp16 Q/K
    rope_kernel<<<10240, 256>>>();
    // fp16 tensor-core attention (128-query tiles)
    attn_tc_kernel<<<dim3(8, 64), 256, ATTN_SMEM_BYTES>>>(sinks, v_nulls);
    // output projection (fp16), split-K=4
    gemm_tc_splitk<<<dim3(8, 8, 4), 256, GEMM_SMEM_BYTES>>>(PARTp, 1024);
    reduce_out_kernel<<<4096, 256>>>(PARTp, W_O_bias, out);
}

// round 12
// speedup vs baseline: 1.0308x; 1.0308x over previous
#include <cuda_runtime.h>
#include <cuda_fp16.h>
#include <math.h>
#include <stdint.h>

#define T_LEN   1024
#define DMODEL  1024
#define QDIM    4096
#define HQ      64
#define HK      16
#define DH      64
#define SILU_SCALE 1.8137993642342178f   /* pi / sqrt(3) */
#define ATTN_SCALE 0.125f                /* DH^-0.5 */

static __device__ float  g_Q[T_LEN * QDIM];        // fp32 Q (pre-rope)
static __device__ float  g_K[T_LEN * DMODEL];      // fp32 K (pre-rope)
static __device__ __half g_Qh[T_LEN * QDIM];       // fp16 Q (post-rope)
static __device__ __half g_Kh[T_LEN * DMODEL];     // fp16 K (post-rope, prescaled)
static __device__ __half g_Vth[DMODEL * T_LEN];    // fp16 V^T: [d][t]
static __device__ __half g_OUTh[T_LEN * QDIM];     // fp16 attention output
static __device__ float  g_part[4 * T_LEN * DMODEL];
// fp16-converted GEMM operands (weights transposed to [N][K])
static __device__ __half g_Xh[T_LEN * DMODEL];
static __device__ __half g_WQt[QDIM * DMODEL];
static __device__ __half g_WKt[DMODEL * DMODEL];
static __device__ __half g_WVt[DMODEL * DMODEL];
static __device__ __half g_WOt[DMODEL * QDIM];

// ===========================================================================
// helpers
// ===========================================================================
__device__ __forceinline__ float f_ex2(float x) { float y; asm("ex2.approx.ftz.f32 %0,%1;" : "=f"(y) : "f"(x)); return y; }
__device__ __forceinline__ float f_lg2(float x) { float y; asm("lg2.approx.ftz.f32 %0,%1;" : "=f"(y) : "f"(x)); return y; }
__device__ __forceinline__ float f_rcp(float x) { float y; asm("rcp.approx.ftz.f32 %0,%1;" : "=f"(y) : "f"(x)); return y; }
__device__ __forceinline__ uint32_t smem_u32(const void* p) {
    uint32_t a;
    asm("{ .reg .u64 t; cvta.to.shared.u64 t, %1; cvt.u32.u64 %0, t; }" : "=r"(a) : "l"(p));
    return a;
}
__device__ __forceinline__ void cp_async16(uint32_t dst, const void* src) {
    asm volatile("cp.async.cg.shared.global [%0], [%1], 16;" :: "r"(dst), "l"(src));
}
#define CP_COMMIT() asm volatile("cp.async.commit_group;" ::: "memory")
#define CP_WAIT0()  asm volatile("cp.async.wait_group 0;"  ::: "memory")
#define CP_WAIT1()  asm volatile("cp.async.wait_group 1;"  ::: "memory")

__device__ __forceinline__ void mma_f16(float* d, const uint32_t* a, const uint32_t* b) {
    asm volatile(
        "mma.sync.aligned.m16n8k16.row.col.f32.f16.f16.f32 "
        "{%0,%1,%2,%3}, {%4,%5,%6,%7}, {%8,%9}, {%0,%1,%2,%3};"
        : "+f"(d[0]), "+f"(d[1]), "+f"(d[2]), "+f"(d[3])
        : "r"(a[0]), "r"(a[1]), "r"(a[2]), "r"(a[3]), "r"(b[0]), "r"(b[1]));
}
__device__ __forceinline__ uint32_t pack_h2(float a, float b) {
    __half2 h = __float22half2_rn(make_float2(a, b));
    return *(uint32_t*)&h;
}
__device__ __forceinline__ uint32_t pack_hh(__half a, __half b) {
    __half2 h = __halves2half2(a, b);
    return *(uint32_t*)&h;
}

// ---------------------------------------------------------------------------
// Convert X to fp16 (z=0) and transpose-convert weights to fp16 [N][K] (z>=1)
// Transposed writes are packed uint32 (2 halves, k-contiguous).
// ---------------------------------------------------------------------------
__global__ __launch_bounds__(256)
void convert_ops(const float* __restrict__ X, const float* __restrict__ WQ,
                 const float* __restrict__ WK, const float* __restrict__ WV,
                 const float* __restrict__ WO)
{
    int z = blockIdx.y;
    int tid = threadIdx.x;

    if (z == 0) {
        int i = blockIdx.x * 256 + tid;
        if (i < (T_LEN * DMODEL) / 4) {
            float4 v = ((const float4*)X)[i];
            uint2 o = { pack_h2(v.x, v.y), pack_h2(v.z, v.w) };
            ((uint2*)g_Xh)[i] = o;
        }
        return;
    }

    const float* src; __half* dst; int Kd, Nd;
    switch (z) {
        case 1:  src = WQ; dst = g_WQt; Kd = DMODEL; Nd = QDIM;   break;
        case 2:  src = WK; dst = g_WKt; Kd = DMODEL; Nd = DMODEL; break;
        case 3:  src = WV; dst = g_WVt; Kd = DMODEL; Nd = DMODEL; break;
        default: src = WO; dst = g_WOt; Kd = QDIM;   Nd = DMODEL; break;
    }
    int ntx = Nd >> 5;
    int tiles = ntx * (Kd >> 5);
    int bx = blockIdx.x;
    if (bx >= tiles) return;
    int tx = bx % ntx, ty = bx / ntx;

    __shared__ __half tile[32][33];
    int r = tid >> 5, c = tid & 31;
#pragma unroll
    for (int i = 0; i < 4; ++i) {
        int row = r + i * 8;
        tile[row][c] = __float2half(src[(size_t)(ty * 32 + row) * Nd + tx * 32 + c]);
    }
    __syncthreads();
    // output tile: 32 n-rows x 16 packed k-words; 256 threads x 2 words
    uint32_t* dw = (uint32_t*)dst;
#pragma unroll
    for (int i = 0; i < 2; ++i) {
        int idx = tid + 256 * i;
        int rr = idx >> 4, c2 = idx & 15;
        uint32_t v = pack_hh(tile[2 * c2][rr], tile[2 * c2 + 1][rr]);
        dw[(size_t)(tx * 32 + rr) * (Kd >> 1) + ty * 16 + c2] = v;
    }
}

// ===========================================================================
// fp16 cp.async 3-stage pipelined GEMM (unchanged from R10)
// ===========================================================================
#define FP_PITCH 20
#define FP_TILE_WORDS (128 * FP_PITCH)
#define NSTAGE 3
#define FP_STG_WORDS (2 * FP_TILE_WORDS)
#define GEMM_SMEM_BYTES (NSTAGE * FP_STG_WORDS * 4)

template <bool BIAS, int OUTK>
__device__ __forceinline__ void gemm_body(
    const __half* __restrict__ A, const __half* __restrict__ Bt,
    const float* __restrict__ bias, float* __restrict__ C, __half* __restrict__ Ch,
    int lda, int ldb, int N, int m0, int n0, int kbase, int kLen)
{
    extern __shared__ uint32_t sm[];
    int tid  = threadIdx.x;
    int lane = tid & 31, wid = tid >> 5;
    int wm = wid & 3, wn = wid >> 2;
    int g = lane >> 2, tg = lane & 3;

    int crow = tid >> 1, cch = tid & 1;

    const __half* Abase = &A[(size_t)(m0 + crow) * lda + kbase + cch * 8];
    const __half* Bbase = &Bt[(size_t)(n0 + crow) * ldb + kbase + cch * 8];

    uint32_t aDst[NSTAGE], bDst[NSTAGE];
#pragma unroll
    for (int s = 0; s < NSTAGE; ++s) {
        aDst[s] = smem_u32(&sm[s * FP_STG_WORDS + crow * FP_PITCH + cch * 4]);
        bDst[s] = smem_u32(&sm[s * FP_STG_WORDS + FP_TILE_WORDS + crow * FP_PITCH + cch * 4]);
    }

#define ISSUE(it_)                                                \
    do {                                                          \
        int s_ = (it_) % NSTAGE;                                  \
        cp_async16(aDst[s_],      Abase + (it_) * 32);            \
        cp_async16(aDst[s_] + 32, Abase + (it_) * 32 + 16);       \
        cp_async16(bDst[s_],      Bbase + (it_) * 32);            \
        cp_async16(bDst[s_] + 32, Bbase + (it_) * 32 + 16);       \
        CP_COMMIT();                                              \
    } while (0)

    float acc[2][8][4];
#pragma unroll
    for (int mf = 0; mf < 2; ++mf)
#pragma unroll
        for (int nf = 0; nf < 8; ++nf)
#pragma unroll
            for (int q = 0; q < 4; ++q) acc[mf][nf][q] = 0.f;

    int NIT = kLen / 32;
    ISSUE(0);
    if (NIT > 1) ISSUE(1);

    for (int it = 0; it < NIT; ++it) {
        int s = it % NSTAGE;
        CP_WAIT1();
        __syncthreads();
        if (it + 2 < NIT) ISSUE(it + 2);

        const uint32_t* As = sm + s * FP_STG_WORDS;
        const uint32_t* Bs = As + FP_TILE_WORDS;
#pragma unroll
        for (int kk = 0; kk < 2; ++kk) {
            uint32_t af[2][4], bf[8][2];
#pragma unroll
            for (int mf = 0; mf < 2; ++mf) {
                const uint32_t* p = &As[(wm * 32 + mf * 16 + g) * FP_PITCH + kk * 8 + tg];
                af[mf][0] = p[0];
                af[mf][1] = p[8 * FP_PITCH];
                af[mf][2] = p[4];
                af[mf][3] = p[8 * FP_PITCH + 4];
            }
#pragma unroll
            for (int nf = 0; nf < 8; ++nf) {
                const uint32_t* p = &Bs[(wn * 64 + nf * 8 + g) * FP_PITCH + kk * 8 + tg];
                bf[nf][0] = p[0];
                bf[nf][1] = p[4];
            }
#pragma unroll
            for (int mf = 0; mf < 2; ++mf)
#pragma unroll
                for (int nf = 0; nf < 8; ++nf)
                    mma_f16(acc[mf][nf], af[mf], bf[nf]);
        }
        __syncthreads();
    }
#undef ISSUE

#pragma unroll
    for (int mf = 0; mf < 2; ++mf) {
        int r0 = m0 + wm * 32 + mf * 16 + g;
#pragma unroll
        for (int nf = 0; nf < 8; ++nf) {
            int c = n0 + wn * 64 + nf * 8 + 2 * tg;
            float b0 = 0.f, b1 = 0.f;
            if (BIAS) { b0 = bias[c]; b1 = bias[c + 1]; }
            if (OUTK == 1) {
                Ch[(size_t)c * T_LEN + r0]           = __float2half(acc[mf][nf][0] + b0);
                Ch[(size_t)(c + 1) * T_LEN + r0]     = __float2half(acc[mf][nf][1] + b1);
                Ch[(size_t)c * T_LEN + r0 + 8]       = __float2half(acc[mf][nf][2] + b0);
                Ch[(size_t)(c + 1) * T_LEN + r0 + 8] = __float2half(acc[mf][nf][3] + b1);
            } else {
                float2 v0 = { acc[mf][nf][0] + b0, acc[mf][nf][1] + b1 };
                float2 v1 = { acc[mf][nf][2] + b0, acc[mf][nf][3] + b1 };
                *(float2*)&C[(size_t)r0 * N + c]       = v0;
                *(float2*)&C[(size_t)(r0 + 8) * N + c] = v1;
            }
        }
    }
}

__global__ __launch_bounds__(256, 2)
void gemm_qkv(const float* __restrict__ b_Q, const float* __restrict__ b_K,
              const float* __restrict__ b_V,
              float* __restrict__ Qo, float* __restrict__ Ko)
{
    int bx = blockIdx.x, m0 = blockIdx.y * 128;
    if (bx < 32)
        gemm_body<true, 0>(g_Xh, g_WQt, b_Q, Qo, nullptr, DMODEL, DMODEL, QDIM, m0, bx * 128, 0, DMODEL);
    else if (bx < 40)
        gemm_body<true, 0>(g_Xh, g_WKt, b_K, Ko, nullptr, DMODEL, DMODEL, DMODEL, m0, (bx - 32) * 128, 0, DMODEL);
    else
        gemm_body<true, 1>(g_Xh, g_WVt, b_V, nullptr, g_Vth, DMODEL, DMODEL, DMODEL, m0, (bx - 40) * 128, 0, DMODEL);
}

__global__ __launch_bounds__(256, 2)
void gemm_tc_splitk(float* __restrict__ Cpart, int kPer)
{
    int z = blockIdx.z;
    gemm_body<false, 0>(g_OUTh, g_WOt, nullptr, Cpart + (size_t)z * T_LEN * DMODEL, nullptr,
                        QDIM, QDIM, DMODEL, blockIdx.y * 128, blockIdx.x * 128, z * kPer, kPer);
}

// ---------------------------------------------------------------------------
// RoPE + key_self/ATTN_SCALE folding; emits fp16 Q and K for attention.
// ---------------------------------------------------------------------------
__global__ __launch_bounds__(256)
void rope_kernel()
{
    int gw   = blockIdx.x * 8 + (threadIdx.x >> 5);
    int lane = threadIdx.x & 31;
    int slot = gw % (HQ + HK);
    int t    = gw / (HQ + HK);

    bool isK = (slot >= HQ);
    const float* ptr = isK ? (g_K + (size_t)t * DMODEL + (slot - HQ) * DH)
                           : (g_Q + (size_t)t * QDIM + slot * DH);
    __half* hptr = isK ? (g_Kh + (size_t)t * DMODEL + (slot - HQ) * DH)
                       : (g_Qh + (size_t)t * QDIM + slot * DH);

    float x1 = ptr[2 * lane];
    float x2 = ptr[2 * lane + 1];

    float inv = 1.0f / powf(10000.0f, (float)(2 * lane) / 64.0f);
    float fr  = (float)t * inv;
    float s, c;
    sincosf(fr, &s, &c);

    float o1 = x1 * c - x2 * s;
    float o2 = x1 * s + x2 * c;

    if (isK) {
        float nrm = x1 * x1 + x2 * x2;
#pragma unroll
        for (int off = 16; off; off >>= 1)
            nrm += __shfl_xor_sync(0xffffffffu, nrm, off);
        float ks  = fmaxf(nrm, 1e-6f);
        float scl = ATTN_SCALE * rsqrtf(ks);
        o1 *= scl;
        o2 *= scl;
    }
    hptr[lane]      = __float2half(o1);
    hptr[lane + 32] = __float2half(o2);
}

// ===========================================================================
// fp16 tensor-core attention (R10 shape) + precomputed diag mask +
// pair-scoped named barrier for Ws visibility.
// ===========================================================================
#define HPITCH 36
#define HTILE_W (64 * HPITCH)
#define ATTN_SMEM_WORDS (5 * HTILE_W + 128 + 64)
#define ATTN_SMEM_BYTES (ATTN_SMEM_WORDS * 4)

__global__ __launch_bounds__(256)
void attn_tc_kernel(const float* __restrict__ sinks, const float* __restrict__ v_nulls)
{
    extern __shared__ uint32_t smu[];
    uint32_t* KsB[2]  = { smu,               smu + HTILE_W };
    uint32_t* VtsB[2] = { smu + 2 * HTILE_W, smu + 3 * HTILE_W };
    uint32_t* Ws      = smu + 4 * HTILE_W;
    float* RSm = (float*)(smu + 5 * HTILE_W);
    float* Tot = RSm + 128;

    int head = blockIdx.y;
    int qt   = (gridDim.x - 1) - blockIdx.x;   // heavy tiles first
    int kvh  = head & (HK - 1);
    int tid  = threadIdx.x;
    int lane = tid & 31, wid = tid >> 5;
    int wm = wid & 3, wn = wid >> 2;
    int g = lane >> 2, tg = lane & 3;
    float sink = sinks[head];

    int crow = tid >> 3, cc = tid & 7;
    uint32_t ksA[2], vtA[2];
#pragma unroll
    for (int b = 0; b < 2; ++b) {
        ksA[b] = smem_u32(&KsB[b][crow * HPITCH + cc * 4]);
        vtA[b] = smem_u32(&VtsB[b][crow * HPITCH + cc * 4]);
    }
    const __half* kSrc  = g_Kh + (size_t)crow * DMODEL + kvh * DH + cc * 8;
    const __half* vtSrc = g_Vth + (size_t)(kvh * DH + crow) * T_LEN + cc * 8;

#define ISSUE_TILES(kt_, b_)                                                     \
    do {                                                                         \
        cp_async16(ksA[b_],                     kSrc + (size_t)(kt_) * 64 * DMODEL); \
        cp_async16(ksA[b_] + 32 * HPITCH * 4,   kSrc + (size_t)((kt_) * 64 + 32) * DMODEL); \
        cp_async16(vtA[b_],                     vtSrc + (kt_) * 64);             \
        cp_async16(vtA[b_] + 32 * HPITCH * 4,   vtSrc + 32 * T_LEN + (kt_) * 64); \
        CP_COMMIT();                                                             \
    } while (0)

    ISSUE_TILES(0, 0);

    // stage Q (fp16) through Ws, then hoist A-fragments to registers
    {
        const uint32_t* qsrc = (const uint32_t*)g_Qh;
#pragma unroll
        for (int i = 0; i < 8; ++i) {
            int idx = tid + 256 * i;
            int r = idx >> 5, wc = idx & 31;
            Ws[r * HPITCH + wc] = qsrc[(size_t)(qt * 64 + r) * (QDIM / 2) + head * (DH / 2) + wc];
        }
    }
    __syncthreads();
    int li0 = wm * 16 + g;
    uint32_t afq[4][4];
    {
        const uint32_t* p0 = &Ws[li0 * HPITCH];
#pragma unroll
        for (int kk = 0; kk < 4; ++kk) {
            afq[kk][0] = p0[kk * 8 + tg];
            afq[kk][1] = p0[8 * HPITCH + kk * 8 + tg];
            afq[kk][2] = p0[kk * 8 + 4 + tg];
            afq[kk][3] = p0[8 * HPITCH + kk * 8 + 4 + tg];
        }
    }

    // precomputed diagonal-tile causal mask (thread-constant): bit=1 -> zero
    unsigned dmask = 0;
#pragma unroll
    for (int nf = 0; nf < 4; ++nf)
#pragma unroll
        for (int q = 0; q < 4; ++q) {
            int row = li0 + ((q >> 1) << 3);
            int col = wn * 32 + nf * 8 + 2 * tg + (q & 1);
            if (col > row) dmask |= 1u << (nf * 4 + q);
        }

    float oacc[4][4];
#pragma unroll
    for (int nf = 0; nf < 4; ++nf)
#pragma unroll
        for (int q = 0; q < 4; ++q) oacc[nf][q] = 0.f;
    float rs0 = 0.f, rs1 = 0.f;

    for (int kt = 0; kt <= qt; ++kt) {
        int b = kt & 1;
        CP_WAIT0();
        __syncthreads();

        if (kt < qt) ISSUE_TILES(kt + 1, b ^ 1);

        const uint32_t* Ks  = KsB[b];
        const uint32_t* Vts = VtsB[b];

        float sacc[4][4];
#pragma unroll
        for (int nf = 0; nf < 4; ++nf)
#pragma unroll
            for (int q = 0; q < 4; ++q) sacc[nf][q] = 0.f;

#pragma unroll
        for (int kk = 0; kk < 4; ++kk) {
            uint32_t bf[4][2];
#pragma unroll
            for (int nf = 0; nf < 4; ++nf) {
                const uint32_t* bp = &Ks[(wn * 32 + nf * 8 + g) * HPITCH + kk * 8 + tg];
                bf[nf][0] = bp[0]; bf[nf][1] = bp[4];
            }
#pragma unroll
            for (int nf = 0; nf < 4; ++nf)
                mma_f16(sacc[nf], afq[kk], bf[nf]);
        }

        unsigned diagbits = (kt == qt) ? dmask : 0u;
#pragma unroll
        for (int nf = 0; nf < 4; ++nf) {
            float w[4];
#pragma unroll
            for (int q = 0; q < 4; ++q) {
                float x = fminf(sacc[nf][q], 60.f);
                float t = f_ex2(x * 1.44269504f);
                float u = f_lg2(1.0f + t);
                float ww = 0.69314718f * u * f_rcp(1.0f + f_ex2(-SILU_SCALE * u));
                if (ww < sink) ww = 0.f;
                if ((diagbits >> (nf * 4 + q)) & 1) ww = 0.f;
                w[q] = ww;
            }
            rs0 += w[0] + w[1];
            rs1 += w[2] + w[3];
            int wc = wn * 16 + nf * 4 + tg;
            Ws[li0 * HPITCH + wc]       = pack_h2(w[0], w[1]);
            Ws[(li0 + 8) * HPITCH + wc] = pack_h2(w[2], w[3]);
        }
        // pair-scoped barrier: WV A-frags only read Ws rows of this wm pair
        asm volatile("bar.sync %0, 64;" :: "r"(wm + 1) : "memory");

#pragma unroll
        for (int kk = 0; kk < 4; ++kk) {
            uint32_t af[4], bf[4][2];
            const uint32_t* ap = &Ws[li0 * HPITCH + kk * 8 + tg];
            af[0] = ap[0];
            af[1] = ap[8 * HPITCH];
            af[2] = ap[4];
            af[3] = ap[8 * HPITCH + 4];
#pragma unroll
            for (int nf = 0; nf < 4; ++nf) {
                const uint32_t* bp = &Vts[(wn * 32 + nf * 8 + g) * HPITCH + kk * 8 + tg];
                bf[nf][0] = bp[0]; bf[nf][1] = bp[4];
            }
#pragma unroll
            for (int nf = 0; nf < 4; ++nf)
                mma_f16(oacc[nf], af, bf[nf]);
        }
    }
#undef ISSUE_TILES

    __syncthreads();
    rs0 += __shfl_xor_sync(0xffffffffu, rs0, 1);
    rs0 += __shfl_xor_sync(0xffffffffu, rs0, 2);
    rs1 += __shfl_xor_sync(0xffffffffu, rs1, 1);
    rs1 += __shfl_xor_sync(0xffffffffu, rs1, 2);
    if (tg == 0) {
        RSm[wid * 16 + g]     = rs0;
        RSm[wid * 16 + 8 + g] = rs1;
    }
    __syncthreads();
    if (tid < 64)
        Tot[tid] = RSm[(tid >> 4) * 16 + (tid & 15)]
                 + RSm[((tid >> 4) + 4) * 16 + (tid & 15)] + sink + 1e-6f;
    __syncthreads();

    float invT0 = 1.0f / Tot[li0];
    float invT1 = 1.0f / Tot[li0 + 8];
#pragma unroll
    for (int nf = 0; nf < 4; ++nf) {
        int dloc = wn * 32 + nf * 8 + 2 * tg;
        float vn0 = v_nulls[head * DH + dloc];
        float vn1 = v_nulls[head * DH + dloc + 1];
        uint32_t o0 = pack_h2((oacc[nf][0] + sink * vn0) * invT0,
                              (oacc[nf][1] + sink * vn1) * invT0);
        uint32_t o1 = pack_h2((oacc[nf][2] + sink * vn0) * invT1,
                              (oacc[nf][3] + sink * vn1) * invT1);
        *(uint32_t*)&g_OUTh[(size_t)(qt * 64 + li0) * QDIM + head * DH + dloc]     = o0;
        *(uint32_t*)&g_OUTh[(size_t)(qt * 64 + li0 + 8) * QDIM + head * DH + dloc] = o1;
    }
}

// ---------------------------------------------------------------------------
// Final reduce: Y = 0.25 * (sum of 4 K-split partials + sum_br bias)
// ---------------------------------------------------------------------------
__global__ __launch_bounds__(256)
void reduce_out_kernel(const float* __restrict__ part, const float* __restrict__ wob,
                       float* __restrict__ out)
{
    int idx = blockIdx.x * 256 + threadIdx.x;
    int d = idx & (DMODEL - 1);
    float s = part[idx] + part[idx + 1048576] + part[idx + 2097152] + part[idx + 3145728];
    float b = wob[d] + wob[DMODEL + d] + wob[2 * DMODEL + d] + wob[3 * DMODEL + d];
    out[idx] = 0.25f * (s + b);
}

// ---------------------------------------------------------------------------
extern "C" void kernel_launch(void* const* d_in, const int* in_sizes, int n_in,
                              void* d_out, int out_size)
{
    const float* X        = (const float*)d_in[0];
    const float* W_Q      = (const float*)d_in[1];
    const float* b_Q      = (const float*)d_in[2];
    const float* W_K      = (const float*)d_in[3];
    const float* b_K      = (const float*)d_in[4];
    const float* W_V      = (const float*)d_in[5];
    const float* b_V      = (const float*)d_in[6];
    const float* sinks    = (const float*)d_in[7];
    const float* v_nulls  = (const float*)d_in[8];
    const float* W_O      = (const float*)d_in[9];
    const float* W_O_bias = (const float*)d_in[10];
    float* out = (float*)d_out;

    float *Qp, *Kp, *PARTp;
    cudaGetSymbolAddress((void**)&Qp,    g_Q);
    cudaGetSymbolAddress((void**)&Kp,    g_K);
    cudaGetSymbolAddress((void**)&PARTp, g_part);

    cudaFuncSetAttribute(gemm_qkv, cudaFuncAttributeMaxDynamicSharedMemorySize, GEMM_SMEM_BYTES);
    cudaFuncSetAttribute(gemm_tc_splitk, cudaFuncAttributeMaxDynamicSharedMemorySize, GEMM_SMEM_BYTES);
    cudaFuncSetAttribute(attn_tc_kernel, cudaFuncAttributeMaxDynamicSharedMemorySize, ATTN_SMEM_BYTES);

    // fp16 conversion: X elementwise (z=0), weights transposed (z=1..4)
    convert_ops<<<dim3(4096, 5), 256>>>(X, W_Q, W_K, W_V, W_O);
    // fused Q/K/V projections (fp16 tensor cores; V written transposed fp16)
    gemm_qkv<<<dim3(48, 8, 1), 256, GEMM_SMEM_BYTES>>>(b_Q, b_K, b_V, Qp, Kp);
    // RoPE + key_self folding -> fp16 Q/K
    rope_kernel<<<10240, 256>>>();
    // fp16 tensor-core attention (64-query tiles, 3 CTAs/SM)
    attn_tc_kernel<<<dim3(16, 64), 256, ATTN_SMEM_BYTES>>>(sinks, v_nulls);
    // output projection (fp16), split-K=4
    gemm_tc_splitk<<<dim3(8, 8, 4), 256, GEMM_SMEM_BYTES>>>(PARTp, 1024);
    reduce_out_kernel<<<4096, 256>>>(PARTp, W_O_bias, out);
}

// round 13
// speedup vs baseline: 1.0549x; 1.0234x over previous
#include <cuda_runtime.h>
#include <cuda_fp16.h>
#include <math.h>
#include <stdint.h>

#define T_LEN   1024
#define DMODEL  1024
#define QDIM    4096
#define HQ      64
#define HK      16
#define DH      64
#define SILU_SCALE 1.8137993642342178f   /* pi / sqrt(3) */
#define ATTN_SCALE 0.125f                /* DH^-0.5 */

static __device__ float  g_Q[T_LEN * QDIM];        // fp32 Q (pre-rope)
static __device__ float  g_K[T_LEN * DMODEL];      // fp32 K (pre-rope)
static __device__ __half g_Qh[T_LEN * QDIM];       // fp16 Q (post-rope)
static __device__ __half g_Kh[T_LEN * DMODEL];     // fp16 K (post-rope, prescaled)
static __device__ __half g_Vth[DMODEL * T_LEN];    // fp16 V^T: [d][t]
static __device__ __half g_OUTh[T_LEN * QDIM];     // fp16 attention output
static __device__ float  g_part[4 * T_LEN * DMODEL];
// fp16-converted GEMM operands (weights transposed to [N][K])
static __device__ __half g_Xh[T_LEN * DMODEL];
static __device__ __half g_WQt[QDIM * DMODEL];
static __device__ __half g_WKt[DMODEL * DMODEL];
static __device__ __half g_WVt[DMODEL * DMODEL];
static __device__ __half g_WOt[DMODEL * QDIM];

// ===========================================================================
// helpers
// ===========================================================================
__device__ __forceinline__ float f_ex2(float x) { float y; asm("ex2.approx.ftz.f32 %0,%1;" : "=f"(y) : "f"(x)); return y; }
__device__ __forceinline__ float f_lg2(float x) { float y; asm("lg2.approx.ftz.f32 %0,%1;" : "=f"(y) : "f"(x)); return y; }
__device__ __forceinline__ float f_rcp(float x) { float y; asm("rcp.approx.ftz.f32 %0,%1;" : "=f"(y) : "f"(x)); return y; }
__device__ __forceinline__ uint32_t smem_u32(const void* p) {
    uint32_t a;
    asm("{ .reg .u64 t; cvta.to.shared.u64 t, %1; cvt.u32.u64 %0, t; }" : "=r"(a) : "l"(p));
    return a;
}
__device__ __forceinline__ void cp_async16(uint32_t dst, const void* src) {
    asm volatile("cp.async.cg.shared.global [%0], [%1], 16;" :: "r"(dst), "l"(src));
}
#define CP_COMMIT() asm volatile("cp.async.commit_group;" ::: "memory")
#define CP_WAIT0()  asm volatile("cp.async.wait_group 0;"  ::: "memory")
#define CP_WAIT1()  asm volatile("cp.async.wait_group 1;"  ::: "memory")

__device__ __forceinline__ void mma_f16(float* d, const uint32_t* a, const uint32_t* b) {
    asm volatile(
        "mma.sync.aligned.m16n8k16.row.col.f32.f16.f16.f32 "
        "{%0,%1,%2,%3}, {%4,%5,%6,%7}, {%8,%9}, {%0,%1,%2,%3};"
        : "+f"(d[0]), "+f"(d[1]), "+f"(d[2]), "+f"(d[3])
        : "r"(a[0]), "r"(a[1]), "r"(a[2]), "r"(a[3]), "r"(b[0]), "r"(b[1]));
}
__device__ __forceinline__ uint32_t pack_h2(float a, float b) {
    __half2 h = __float22half2_rn(make_float2(a, b));
    return *(uint32_t*)&h;
}
__device__ __forceinline__ uint32_t pack_hh(__half a, __half b) {
    __half2 h = __halves2half2(a, b);
    return *(uint32_t*)&h;
}

// ---------------------------------------------------------------------------
// Convert X to fp16 (z=0) and transpose-convert weights to fp16 [N][K] (z>=1)
// ---------------------------------------------------------------------------
__global__ __launch_bounds__(256)
void convert_ops(const float* __restrict__ X, const float* __restrict__ WQ,
                 const float* __restrict__ WK, const float* __restrict__ WV,
                 const float* __restrict__ WO)
{
    int z = blockIdx.y;
    int tid = threadIdx.x;

    if (z == 0) {
        int i = blockIdx.x * 256 + tid;
        if (i < (T_LEN * DMODEL) / 4) {
            float4 v = ((const float4*)X)[i];
            uint2 o = { pack_h2(v.x, v.y), pack_h2(v.z, v.w) };
            ((uint2*)g_Xh)[i] = o;
        }
        return;
    }

    const float* src; __half* dst; int Kd, Nd;
    switch (z) {
        case 1:  src = WQ; dst = g_WQt; Kd = DMODEL; Nd = QDIM;   break;
        case 2:  src = WK; dst = g_WKt; Kd = DMODEL; Nd = DMODEL; break;
        case 3:  src = WV; dst = g_WVt; Kd = DMODEL; Nd = DMODEL; break;
        default: src = WO; dst = g_WOt; Kd = QDIM;   Nd = DMODEL; break;
    }
    int ntx = Nd >> 5;
    int tiles = ntx * (Kd >> 5);
    int bx = blockIdx.x;
    if (bx >= tiles) return;
    int tx = bx % ntx, ty = bx / ntx;

    __shared__ __half tile[32][33];
    int r = tid >> 5, c = tid & 31;
#pragma unroll
    for (int i = 0; i < 4; ++i) {
        int row = r + i * 8;
        tile[row][c] = __float2half(src[(size_t)(ty * 32 + row) * Nd + tx * 32 + c]);
    }
    __syncthreads();
    uint32_t* dw = (uint32_t*)dst;
#pragma unroll
    for (int i = 0; i < 2; ++i) {
        int idx = tid + 256 * i;
        int rr = idx >> 4, c2 = idx & 15;
        uint32_t v = pack_hh(tile[2 * c2][rr], tile[2 * c2 + 1][rr]);
        dw[(size_t)(tx * 32 + rr) * (Kd >> 1) + ty * 16 + c2] = v;
    }
}

// ===========================================================================
// fp16 cp.async 3-stage pipelined GEMM, BK=64: 128x128 tile, 8 warps (4m x 2n)
// Row = 64 halves (pitch 36 words). 64 HMMA/warp per iteration, 2 barriers.
// ===========================================================================
#define FP_PITCH 36                       // words per 64-half row (32 data + 4 pad)
#define FP_TILE_WORDS (128 * FP_PITCH)
#define NSTAGE 3
#define FP_STG_WORDS (2 * FP_TILE_WORDS)
#define GEMM_SMEM_BYTES (NSTAGE * FP_STG_WORDS * 4)   /* 110592 */

template <bool BIAS, int OUTK>
__device__ __forceinline__ void gemm_body(
    const __half* __restrict__ A, const __half* __restrict__ Bt,
    const float* __restrict__ bias, float* __restrict__ C, __half* __restrict__ Ch,
    int lda, int ldb, int N, int m0, int n0, int kbase, int kLen)
{
    extern __shared__ uint32_t sm[];
    int tid  = threadIdx.x;
    int lane = tid & 31, wid = tid >> 5;
    int wm = wid & 3, wn = wid >> 2;
    int g = lane >> 2, tg = lane & 3;

    int crow = tid >> 1, cch = tid & 1;    // row 0..127, 64B half of row

    const __half* Abase = &A[(size_t)(m0 + crow) * lda + kbase + cch * 32];
    const __half* Bbase = &Bt[(size_t)(n0 + crow) * ldb + kbase + cch * 32];

    uint32_t aDst[NSTAGE], bDst[NSTAGE];
#pragma unroll
    for (int s = 0; s < NSTAGE; ++s) {
        aDst[s] = smem_u32(&sm[s * FP_STG_WORDS + crow * FP_PITCH + cch * 16]);
        bDst[s] = smem_u32(&sm[s * FP_STG_WORDS + FP_TILE_WORDS + crow * FP_PITCH + cch * 16]);
    }

#define ISSUE(it_)                                                    \
    do {                                                              \
        int s_ = (it_) % NSTAGE;                                      \
        _Pragma("unroll")                                             \
        for (int j = 0; j < 4; ++j)                                   \
            cp_async16(aDst[s_] + j * 16, Abase + (it_) * 64 + j * 8);\
        _Pragma("unroll")                                             \
        for (int j = 0; j < 4; ++j)                                   \
            cp_async16(bDst[s_] + j * 16, Bbase + (it_) * 64 + j * 8);\
        CP_COMMIT();                                                  \
    } while (0)

    float acc[2][8][4];
#pragma unroll
    for (int mf = 0; mf < 2; ++mf)
#pragma unroll
        for (int nf = 0; nf < 8; ++nf)
#pragma unroll
            for (int q = 0; q < 4; ++q) acc[mf][nf][q] = 0.f;

    int NIT = kLen / 64;
    ISSUE(0);
    if (NIT > 1) ISSUE(1);

    for (int it = 0; it < NIT; ++it) {
        int s = it % NSTAGE;
        CP_WAIT1();
        __syncthreads();
        if (it + 2 < NIT) ISSUE(it + 2);

        const uint32_t* As = sm + s * FP_STG_WORDS;
        const uint32_t* Bs = As + FP_TILE_WORDS;
#pragma unroll
        for (int kk = 0; kk < 4; ++kk) {
            uint32_t af[2][4], bf[8][2];
#pragma unroll
            for (int mf = 0; mf < 2; ++mf) {
                const uint32_t* p = &As[(wm * 32 + mf * 16 + g) * FP_PITCH + kk * 8 + tg];
                af[mf][0] = p[0];
                af[mf][1] = p[8 * FP_PITCH];
                af[mf][2] = p[4];
                af[mf][3] = p[8 * FP_PITCH + 4];
            }
#pragma unroll
            for (int nf = 0; nf < 8; ++nf) {
                const uint32_t* p = &Bs[(wn * 64 + nf * 8 + g) * FP_PITCH + kk * 8 + tg];
                bf[nf][0] = p[0];
                bf[nf][1] = p[4];
            }
#pragma unroll
            for (int mf = 0; mf < 2; ++mf)
#pragma unroll
                for (int nf = 0; nf < 8; ++nf)
                    mma_f16(acc[mf][nf], af[mf], bf[nf]);
        }
        __syncthreads();
    }
#undef ISSUE

#pragma unroll
    for (int mf = 0; mf < 2; ++mf) {
        int r0 = m0 + wm * 32 + mf * 16 + g;
#pragma unroll
        for (int nf = 0; nf < 8; ++nf) {
            int c = n0 + wn * 64 + nf * 8 + 2 * tg;
            float b0 = 0.f, b1 = 0.f;
            if (BIAS) { b0 = bias[c]; b1 = bias[c + 1]; }
            if (OUTK == 1) {
                Ch[(size_t)c * T_LEN + r0]           = __float2half(acc[mf][nf][0] + b0);
                Ch[(size_t)(c + 1) * T_LEN + r0]     = __float2half(acc[mf][nf][1] + b1);
                Ch[(size_t)c * T_LEN + r0 + 8]       = __float2half(acc[mf][nf][2] + b0);
                Ch[(size_t)(c + 1) * T_LEN + r0 + 8] = __float2half(acc[mf][nf][3] + b1);
            } else {
                float2 v0 = { acc[mf][nf][0] + b0, acc[mf][nf][1] + b1 };
                float2 v1 = { acc[mf][nf][2] + b0, acc[mf][nf][3] + b1 };
                *(float2*)&C[(size_t)r0 * N + c]       = v0;
                *(float2*)&C[(size_t)(r0 + 8) * N + c] = v1;
            }
        }
    }
}

__global__ __launch_bounds__(256, 2)
void gemm_qkv(const float* __restrict__ b_Q, const float* __restrict__ b_K,
              const float* __restrict__ b_V,
              float* __restrict__ Qo, float* __restrict__ Ko)
{
    int bx = blockIdx.x, m0 = blockIdx.y * 128;
    if (bx < 32)
        gemm_body<true, 0>(g_Xh, g_WQt, b_Q, Qo, nullptr, DMODEL, DMODEL, QDIM, m0, bx * 128, 0, DMODEL);
    else if (bx < 40)
        gemm_body<true, 0>(g_Xh, g_WKt, b_K, Ko, nullptr, DMODEL, DMODEL, DMODEL, m0, (bx - 32) * 128, 0, DMODEL);
    else
        gemm_body<true, 1>(g_Xh, g_WVt, b_V, nullptr, g_Vth, DMODEL, DMODEL, DMODEL, m0, (bx - 40) * 128, 0, DMODEL);
}

__global__ __launch_bounds__(256, 2)
void gemm_tc_splitk(float* __restrict__ Cpart, int kPer)
{
    int z = blockIdx.z;
    gemm_body<false, 0>(g_OUTh, g_WOt, nullptr, Cpart + (size_t)z * T_LEN * DMODEL, nullptr,
                        QDIM, QDIM, DMODEL, blockIdx.y * 128, blockIdx.x * 128, z * kPer, kPer);
}

// ---------------------------------------------------------------------------
// RoPE + key_self/ATTN_SCALE folding; emits fp16 Q and K.
// inv_freq via ex2.approx (same ~2e-7 rel accuracy as powf here).
// ---------------------------------------------------------------------------
__global__ __launch_bounds__(256)
void rope_kernel()
{
    int gw   = blockIdx.x * 8 + (threadIdx.x >> 5);
    int lane = threadIdx.x & 31;
    int slot = gw % (HQ + HK);
    int t    = gw / (HQ + HK);

    bool isK = (slot >= HQ);
    const float* ptr = isK ? (g_K + (size_t)t * DMODEL + (slot - HQ) * DH)
                           : (g_Q + (size_t)t * QDIM + slot * DH);
    __half* hptr = isK ? (g_Kh + (size_t)t * DMODEL + (slot - HQ) * DH)
                       : (g_Qh + (size_t)t * QDIM + slot * DH);

    float x1 = ptr[2 * lane];
    float x2 = ptr[2 * lane + 1];

    // inv = 10000^(-2*lane/64) = 2^(-lane * log2(10000)/32)
    float inv = f_ex2((float)lane * -0.41524100779716735f);
    float fr  = (float)t * inv;
    float s, c;
    sincosf(fr, &s, &c);

    float o1 = x1 * c - x2 * s;
    float o2 = x1 * s + x2 * c;

    if (isK) {
        float nrm = x1 * x1 + x2 * x2;
#pragma unroll
        for (int off = 16; off; off >>= 1)
            nrm += __shfl_xor_sync(0xffffffffu, nrm, off);
        float ks  = fmaxf(nrm, 1e-6f);
        float scl = ATTN_SCALE * rsqrtf(ks);
        o1 *= scl;
        o2 *= scl;
    }
    hptr[lane]      = __float2half(o1);
    hptr[lane + 32] = __float2half(o2);
}

// ===========================================================================
// fp16 tensor-core attention (exact R10 version, 80.7us known-good)
// ===========================================================================
#define HPITCH 36
#define HTILE_W (64 * HPITCH)
#define ATTN_SMEM_WORDS (5 * HTILE_W + 128 + 64)
#define ATTN_SMEM_BYTES (ATTN_SMEM_WORDS * 4)

__global__ __launch_bounds__(256)
void attn_tc_kernel(const float* __restrict__ sinks, const float* __restrict__ v_nulls)
{
    extern __shared__ uint32_t smu[];
    uint32_t* KsB[2]  = { smu,               smu + HTILE_W };
    uint32_t* VtsB[2] = { smu + 2 * HTILE_W, smu + 3 * HTILE_W };
    uint32_t* Ws      = smu + 4 * HTILE_W;
    float* RSm = (float*)(smu + 5 * HTILE_W);
    float* Tot = RSm + 128;

    int head = blockIdx.y;
    int qt   = (gridDim.x - 1) - blockIdx.x;   // heavy tiles first
    int kvh  = head & (HK - 1);
    int tid  = threadIdx.x;
    int lane = tid & 31, wid = tid >> 5;
    int wm = wid & 3, wn = wid >> 2;
    int g = lane >> 2, tg = lane & 3;
    float sink = sinks[head];

    int crow = tid >> 3, cc = tid & 7;
    uint32_t ksA[2], vtA[2];
#pragma unroll
    for (int b = 0; b < 2; ++b) {
        ksA[b] = smem_u32(&KsB[b][crow * HPITCH + cc * 4]);
        vtA[b] = smem_u32(&VtsB[b][crow * HPITCH + cc * 4]);
    }
    const __half* kSrc  = g_Kh + (size_t)crow * DMODEL + kvh * DH + cc * 8;
    const __half* vtSrc = g_Vth + (size_t)(kvh * DH + crow) * T_LEN + cc * 8;

#define ISSUE_TILES(kt_, b_)                                                     \
    do {                                                                         \
        cp_async16(ksA[b_],                     kSrc + (size_t)(kt_) * 64 * DMODEL); \
        cp_async16(ksA[b_] + 32 * HPITCH * 4,   kSrc + (size_t)((kt_) * 64 + 32) * DMODEL); \
        cp_async16(vtA[b_],                     vtSrc + (kt_) * 64);             \
        cp_async16(vtA[b_] + 32 * HPITCH * 4,   vtSrc + 32 * T_LEN + (kt_) * 64); \
        CP_COMMIT();                                                             \
    } while (0)

    ISSUE_TILES(0, 0);

    {
        const uint32_t* qsrc = (const uint32_t*)g_Qh;
#pragma unroll
        for (int i = 0; i < 8; ++i) {
            int idx = tid + 256 * i;
            int r = idx >> 5, wc = idx & 31;
            Ws[r * HPITCH + wc] = qsrc[(size_t)(qt * 64 + r) * (QDIM / 2) + head * (DH / 2) + wc];
        }
    }
    __syncthreads();
    int li0 = wm * 16 + g;
    uint32_t afq[4][4];
    {
        const uint32_t* p0 = &Ws[li0 * HPITCH];
#pragma unroll
        for (int kk = 0; kk < 4; ++kk) {
            afq[kk][0] = p0[kk * 8 + tg];
            afq[kk][1] = p0[8 * HPITCH + kk * 8 + tg];
            afq[kk][2] = p0[kk * 8 + 4 + tg];
            afq[kk][3] = p0[8 * HPITCH + kk * 8 + 4 + tg];
        }
    }

    float oacc[4][4];
#pragma unroll
    for (int nf = 0; nf < 4; ++nf)
#pragma unroll
        for (int q = 0; q < 4; ++q) oacc[nf][q] = 0.f;
    float rs0 = 0.f, rs1 = 0.f;
    int gi0 = qt * 64 + li0;

    for (int kt = 0; kt <= qt; ++kt) {
        int b = kt & 1;
        CP_WAIT0();
        __syncthreads();

        if (kt < qt) ISSUE_TILES(kt + 1, b ^ 1);

        const uint32_t* Ks  = KsB[b];
        const uint32_t* Vts = VtsB[b];

        float sacc[4][4];
#pragma unroll
        for (int nf = 0; nf < 4; ++nf)
#pragma unroll
            for (int q = 0; q < 4; ++q) sacc[nf][q] = 0.f;

#pragma unroll
        for (int kk = 0; kk < 4; ++kk) {
            uint32_t bf[4][2];
#pragma unroll
            for (int nf = 0; nf < 4; ++nf) {
                const uint32_t* bp = &Ks[(wn * 32 + nf * 8 + g) * HPITCH + kk * 8 + tg];
                bf[nf][0] = bp[0]; bf[nf][1] = bp[4];
            }
#pragma unroll
            for (int nf = 0; nf < 4; ++nf)
                mma_f16(sacc[nf], afq[kk], bf[nf]);
        }

        bool diag = (kt == qt);
#pragma unroll
        for (int nf = 0; nf < 4; ++nf) {
            int ljc = wn * 32 + nf * 8 + 2 * tg;
            int gj  = kt * 64 + ljc;
            float w[4];
#pragma unroll
            for (int q = 0; q < 4; ++q) {
                float x = fminf(sacc[nf][q], 60.f);
                float t = f_ex2(x * 1.44269504f);
                float u = f_lg2(1.0f + t);
                float ww = 0.69314718f * u * f_rcp(1.0f + f_ex2(-SILU_SCALE * u));
                int gi = gi0 + ((q >> 1) << 3);
                int gjj = gj + (q & 1);
                if ((diag && gjj > gi) || ww < sink) ww = 0.f;
                w[q] = ww;
            }
            rs0 += w[0] + w[1];
            rs1 += w[2] + w[3];
            int wc = wn * 16 + nf * 4 + tg;
            Ws[li0 * HPITCH + wc]       = pack_h2(w[0], w[1]);
            Ws[(li0 + 8) * HPITCH + wc] = pack_h2(w[2], w[3]);
        }
        __syncthreads();

#pragma unroll
        for (int kk = 0; kk < 4; ++kk) {
            uint32_t af[4], bf[4][2];
            const uint32_t* ap = &Ws[li0 * HPITCH + kk * 8 + tg];
            af[0] = ap[0];
            af[1] = ap[8 * HPITCH];
            af[2] = ap[4];
            af[3] = ap[8 * HPITCH + 4];
#pragma unroll
            for (int nf = 0; nf < 4; ++nf) {
                const uint32_t* bp = &Vts[(wn * 32 + nf * 8 + g) * HPITCH + kk * 8 + tg];
                bf[nf][0] = bp[0]; bf[nf][1] = bp[4];
            }
#pragma unroll
            for (int nf = 0; nf < 4; ++nf)
                mma_f16(oacc[nf], af, bf[nf]);
        }
    }
#undef ISSUE_TILES

    __syncthreads();
    rs0 += __shfl_xor_sync(0xffffffffu, rs0, 1);
    rs0 += __shfl_xor_sync(0xffffffffu, rs0, 2);
    rs1 += __shfl_xor_sync(0xffffffffu, rs1, 1);
    rs1 += __shfl_xor_sync(0xffffffffu, rs1, 2);
    if (tg == 0) {
        RSm[wid * 16 + g]     = rs0;
        RSm[wid * 16 + 8 + g] = rs1;
    }
    __syncthreads();
    if (tid < 64)
        Tot[tid] = RSm[(tid >> 4) * 16 + (tid & 15)]
                 + RSm[((tid >> 4) + 4) * 16 + (tid & 15)] + sink + 1e-6f;
    __syncthreads();

    float invT0 = 1.0f / Tot[li0];
    float invT1 = 1.0f / Tot[li0 + 8];
#pragma unroll
    for (int nf = 0; nf < 4; ++nf) {
        int dloc = wn * 32 + nf * 8 + 2 * tg;
        float vn0 = v_nulls[head * DH + dloc];
        float vn1 = v_nulls[head * DH + dloc + 1];
        uint32_t o0 = pack_h2((oacc[nf][0] + sink * vn0) * invT0,
                              (oacc[nf][1] + sink * vn1) * invT0);
        uint32_t o1 = pack_h2((oacc[nf][2] + sink * vn0) * invT1,
                              (oacc[nf][3] + sink * vn1) * invT1);
        *(uint32_t*)&g_OUTh[(size_t)(qt * 64 + li0) * QDIM + head * DH + dloc]     = o0;
        *(uint32_t*)&g_OUTh[(size_t)(qt * 64 + li0 + 8) * QDIM + head * DH + dloc] = o1;
    }
}

// ---------------------------------------------------------------------------
// Final reduce: Y = 0.25 * (sum of 4 K-split partials + sum_br bias)
// ---------------------------------------------------------------------------
__global__ __launch_bounds__(256)
void reduce_out_kernel(const float* __restrict__ part, const float* __restrict__ wob,
                       float* __restrict__ out)
{
    int idx = blockIdx.x * 256 + threadIdx.x;
    int d = idx & (DMODEL - 1);
    float s = part[idx] + part[idx + 1048576] + part[idx + 2097152] + part[idx + 3145728];
    float b = wob[d] + wob[DMODEL + d] + wob[2 * DMODEL + d] + wob[3 * DMODEL + d];
    out[idx] = 0.25f * (s + b);
}

// ---------------------------------------------------------------------------
extern "C" void kernel_launch(void* const* d_in, const int* in_sizes, int n_in,
                              void* d_out, int out_size)
{
    const float* X        = (const float*)d_in[0];
    const float* W_Q      = (const float*)d_in[1];
    const float* b_Q      = (const float*)d_in[2];
    const float* W_K      = (const float*)d_in[3];
    const float* b_K      = (const float*)d_in[4];
    const float* W_V      = (const float*)d_in[5];
    const float* b_V      = (const float*)d_in[6];
    const float* sinks    = (const float*)d_in[7];
    const float* v_nulls  = (const float*)d_in[8];
    const float* W_O      = (const float*)d_in[9];
    const float* W_O_bias = (const float*)d_in[10];
    float* out = (float*)d_out;

    float *Qp, *Kp, *PARTp;
    cudaGetSymbolAddress((void**)&Qp,    g_Q);
    cudaGetSymbolAddress((void**)&Kp,    g_K);
    cudaGetSymbolAddress((void**)&PARTp, g_part);

    cudaFuncSetAttribute(gemm_qkv, cudaFuncAttributeMaxDynamicSharedMemorySize, GEMM_SMEM_BYTES);
    cudaFuncSetAttribute(gemm_tc_splitk, cudaFuncAttributeMaxDynamicSharedMemorySize, GEMM_SMEM_BYTES);
    cudaFuncSetAttribute(attn_tc_kernel, cudaFuncAttributeMaxDynamicSharedMemorySize, ATTN_SMEM_BYTES);

    // fp16 conversion: X elementwise (z=0), weights transposed (z=1..4)
    convert_ops<<<dim3(4096, 5), 256>>>(X, W_Q, W_K, W_V, W_O);
    // fused Q/K/V projections (fp16, BK=64)
    gemm_qkv<<<dim3(48, 8, 1), 256, GEMM_SMEM_BYTES>>>(b_Q, b_K, b_V, Qp, Kp);
    // RoPE + key_self folding -> fp16 Q/K
    rope_kernel<<<10240, 256>>>();
    // fp16 tensor-core attention
    attn_tc_kernel<<<dim3(16, 64), 256, ATTN_SMEM_BYTES>>>(sinks, v_nulls);
    // output projection (fp16, BK=64), split-K=4
    gemm_tc_splitk<<<dim3(8, 8, 4), 256, GEMM_SMEM_BYTES>>>(PARTp, 1024);
    reduce_out_kernel<<<4096, 256>>>(PARTp, W_O_bias, out);
}

// round 14
// speedup vs baseline: 1.2459x; 1.1811x over previous
#include <cuda_runtime.h>
#include <cuda_fp16.h>
#include <math.h>
#include <stdint.h>

#define T_LEN   1024
#define DMODEL  1024
#define QDIM    4096
#define HQ      64
#define HK      16
#define DH      64
#define SILU_SCALE 1.8137993642342178f   /* pi / sqrt(3) */
#define ATTN_SCALE 0.125f                /* DH^-0.5 */

static __device__ __half g_Qh[T_LEN * QDIM];       // fp16 Q (qkv out, then roped)
static __device__ __half g_Kh[T_LEN * DMODEL];     // fp16 K (qkv out, then roped+prescaled)
static __device__ __half g_Vth[DMODEL * T_LEN];    // fp16 V^T: [d][t]
static __device__ __half g_OUTh[T_LEN * QDIM];     // fp16 attention output
static __device__ float  g_part[4 * T_LEN * DMODEL];
// fp16-converted GEMM operands (weights transposed to [N][K])
static __device__ __half g_Xh[T_LEN * DMODEL];
static __device__ __half g_WQt[QDIM * DMODEL];
static __device__ __half g_WKt[DMODEL * DMODEL];
static __device__ __half g_WVt[DMODEL * DMODEL];
static __device__ __half g_WOt[DMODEL * QDIM];

// ===========================================================================
// helpers
// ===========================================================================
__device__ __forceinline__ float f_ex2(float x) { float y; asm("ex2.approx.ftz.f32 %0,%1;" : "=f"(y) : "f"(x)); return y; }
__device__ __forceinline__ float f_lg2(float x) { float y; asm("lg2.approx.ftz.f32 %0,%1;" : "=f"(y) : "f"(x)); return y; }
__device__ __forceinline__ float f_rcp(float x) { float y; asm("rcp.approx.ftz.f32 %0,%1;" : "=f"(y) : "f"(x)); return y; }
__device__ __forceinline__ uint32_t smem_u32(const void* p) {
    uint32_t a;
    asm("{ .reg .u64 t; cvta.to.shared.u64 t, %1; cvt.u32.u64 %0, t; }" : "=r"(a) : "l"(p));
    return a;
}
__device__ __forceinline__ void cp_async16(uint32_t dst, const void* src) {
    asm volatile("cp.async.cg.shared.global [%0], [%1], 16;" :: "r"(dst), "l"(src));
}
#define CP_COMMIT() asm volatile("cp.async.commit_group;" ::: "memory")
#define CP_WAIT0()  asm volatile("cp.async.wait_group 0;"  ::: "memory")
#define CP_WAIT1()  asm volatile("cp.async.wait_group 1;"  ::: "memory")

__device__ __forceinline__ void mma_f16(float* d, const uint32_t* a, const uint32_t* b) {
    asm volatile(
        "mma.sync.aligned.m16n8k16.row.col.f32.f16.f16.f32 "
        "{%0,%1,%2,%3}, {%4,%5,%6,%7}, {%8,%9}, {%0,%1,%2,%3};"
        : "+f"(d[0]), "+f"(d[1]), "+f"(d[2]), "+f"(d[3])
        : "r"(a[0]), "r"(a[1]), "r"(a[2]), "r"(a[3]), "r"(b[0]), "r"(b[1]));
}
__device__ __forceinline__ void ldm_x4(uint32_t addr, uint32_t& r0, uint32_t& r1,
                                       uint32_t& r2, uint32_t& r3) {
    asm volatile("ldmatrix.sync.aligned.m8n8.x4.shared.b16 {%0,%1,%2,%3}, [%4];"
                 : "=r"(r0), "=r"(r1), "=r"(r2), "=r"(r3) : "r"(addr));
}
__device__ __forceinline__ void stm_x4(uint32_t addr, uint32_t r0, uint32_t r1,
                                       uint32_t r2, uint32_t r3) {
    asm volatile("stmatrix.sync.aligned.m8n8.x4.shared.b16 [%0], {%1,%2,%3,%4};"
                 :: "r"(addr), "r"(r0), "r"(r1), "r"(r2), "r"(r3) : "memory");
}
__device__ __forceinline__ uint32_t pack_h2(float a, float b) {
    __half2 h = __float22half2_rn(make_float2(a, b));
    return *(uint32_t*)&h;
}
__device__ __forceinline__ uint32_t pack_hh(__half a, __half b) {
    __half2 h = __halves2half2(a, b);
    return *(uint32_t*)&h;
}

// ---------------------------------------------------------------------------
// Convert X to fp16 (z=0) and transpose-convert weights to fp16 [N][K] (z>=1)
// ---------------------------------------------------------------------------
__global__ __launch_bounds__(256)
void convert_ops(const float* __restrict__ X, const float* __restrict__ WQ,
                 const float* __restrict__ WK, const float* __restrict__ WV,
                 const float* __restrict__ WO)
{
    int z = blockIdx.y;
    int tid = threadIdx.x;

    if (z == 0) {
        int i = blockIdx.x * 256 + tid;
        if (i < (T_LEN * DMODEL) / 4) {
            float4 v = ((const float4*)X)[i];
            uint2 o = { pack_h2(v.x, v.y), pack_h2(v.z, v.w) };
            ((uint2*)g_Xh)[i] = o;
        }
        return;
    }

    const float* src; __half* dst; int Kd, Nd;
    switch (z) {
        case 1:  src = WQ; dst = g_WQt; Kd = DMODEL; Nd = QDIM;   break;
        case 2:  src = WK; dst = g_WKt; Kd = DMODEL; Nd = DMODEL; break;
        case 3:  src = WV; dst = g_WVt; Kd = DMODEL; Nd = DMODEL; break;
        default: src = WO; dst = g_WOt; Kd = QDIM;   Nd = DMODEL; break;
    }
    int ntx = Nd >> 5;
    int tiles = ntx * (Kd >> 5);
    int bx = blockIdx.x;
    if (bx >= tiles) return;
    int tx = bx % ntx, ty = bx / ntx;

    __shared__ __half tile[32][33];
    int r = tid >> 5, c = tid & 31;
#pragma unroll
    for (int i = 0; i < 4; ++i) {
        int row = r + i * 8;
        tile[row][c] = __float2half(src[(size_t)(ty * 32 + row) * Nd + tx * 32 + c]);
    }
    __syncthreads();
    uint32_t* dw = (uint32_t*)dst;
#pragma unroll
    for (int i = 0; i < 2; ++i) {
        int idx = tid + 256 * i;
        int rr = idx >> 4, c2 = idx & 15;
        uint32_t v = pack_hh(tile[2 * c2][rr], tile[2 * c2 + 1][rr]);
        dw[(size_t)(tx * 32 + rr) * (Kd >> 1) + ty * 16 + c2] = v;
    }
}

// ===========================================================================
// fp16 cp.async 3-stage pipelined GEMM, BK=64, ldmatrix fragment loads.
// OUTK: 0 = fp32 rows (partials), 1 = fp16 transposed (V^T), 2 = fp16 rows
// ===========================================================================
#define FP_PITCH 36
#define FP_TILE_WORDS (128 * FP_PITCH)
#define NSTAGE 3
#define FP_STG_WORDS (2 * FP_TILE_WORDS)
#define GEMM_SMEM_BYTES (NSTAGE * FP_STG_WORDS * 4)

template <bool BIAS, int OUTK>
__device__ __forceinline__ void gemm_body(
    const __half* __restrict__ A, const __half* __restrict__ Bt,
    const float* __restrict__ bias, float* __restrict__ C, __half* __restrict__ Ch,
    int lda, int ldb, int N, int m0, int n0, int kbase, int kLen)
{
    extern __shared__ uint32_t sm[];
    int tid  = threadIdx.x;
    int lane = tid & 31, wid = tid >> 5;
    int wm = wid & 3, wn = wid >> 2;
    int g = lane >> 2, tg = lane & 3;
    int m8 = lane >> 3, rr = lane & 7;

    int crow = tid >> 1, cch = tid & 1;

    const __half* Abase = &A[(size_t)(m0 + crow) * lda + kbase + cch * 32];
    const __half* Bbase = &Bt[(size_t)(n0 + crow) * ldb + kbase + cch * 32];

    uint32_t stageA[NSTAGE], stageB[NSTAGE];
    uint32_t aDst[NSTAGE], bDst[NSTAGE];
#pragma unroll
    for (int s = 0; s < NSTAGE; ++s) {
        stageA[s] = smem_u32(sm + s * FP_STG_WORDS);
        stageB[s] = stageA[s] + FP_TILE_WORDS * 4;
        aDst[s] = stageA[s] + (crow * FP_PITCH + cch * 16) * 4;
        bDst[s] = stageB[s] + (crow * FP_PITCH + cch * 16) * 4;
    }

    // ldmatrix fragment offsets (bytes)
    uint32_t aoffG[2], broffG[4];
#pragma unroll
    for (int mf = 0; mf < 2; ++mf)
        aoffG[mf] = ((wm * 32 + mf * 16 + (m8 & 1) * 8 + rr) * FP_PITCH + (m8 >> 1) * 4) * 4;
#pragma unroll
    for (int p = 0; p < 4; ++p)
        broffG[p] = ((wn * 64 + (2 * p + (m8 >> 1)) * 8 + rr) * FP_PITCH + (m8 & 1) * 4) * 4;

#define ISSUE(it_)                                                    \
    do {                                                              \
        int s_ = (it_) % NSTAGE;                                      \
        _Pragma("unroll")                                             \
        for (int j = 0; j < 4; ++j)                                   \
            cp_async16(aDst[s_] + j * 16, Abase + (it_) * 64 + j * 8);\
        _Pragma("unroll")                                             \
        for (int j = 0; j < 4; ++j)                                   \
            cp_async16(bDst[s_] + j * 16, Bbase + (it_) * 64 + j * 8);\
        CP_COMMIT();                                                  \
    } while (0)

    float acc[2][8][4];
#pragma unroll
    for (int mf = 0; mf < 2; ++mf)
#pragma unroll
        for (int nf = 0; nf < 8; ++nf)
#pragma unroll
            for (int q = 0; q < 4; ++q) acc[mf][nf][q] = 0.f;

    int NIT = kLen / 64;
    ISSUE(0);
    if (NIT > 1) ISSUE(1);

    for (int it = 0; it < NIT; ++it) {
        int s = it % NSTAGE;
        CP_WAIT1();
        __syncthreads();
        if (it + 2 < NIT) ISSUE(it + 2);

#pragma unroll
        for (int kk = 0; kk < 4; ++kk) {
            uint32_t af[2][4];
            ldm_x4(stageA[s] + aoffG[0] + kk * 32, af[0][0], af[0][1], af[0][2], af[0][3]);
            ldm_x4(stageA[s] + aoffG[1] + kk * 32, af[1][0], af[1][1], af[1][2], af[1][3]);
#pragma unroll
            for (int p = 0; p < 4; ++p) {
                uint32_t b0, b1, b2, b3;
                ldm_x4(stageB[s] + broffG[p] + kk * 32, b0, b1, b2, b3);
                uint32_t bfa[2] = { b0, b1 }, bfb[2] = { b2, b3 };
                mma_f16(acc[0][2 * p],     af[0], bfa);
                mma_f16(acc[1][2 * p],     af[1], bfa);
                mma_f16(acc[0][2 * p + 1], af[0], bfb);
                mma_f16(acc[1][2 * p + 1], af[1], bfb);
            }
        }
        __syncthreads();
    }
#undef ISSUE

#pragma unroll
    for (int mf = 0; mf < 2; ++mf) {
        int r0 = m0 + wm * 32 + mf * 16 + g;
#pragma unroll
        for (int nf = 0; nf < 8; ++nf) {
            int c = n0 + wn * 64 + nf * 8 + 2 * tg;
            float b0 = 0.f, b1 = 0.f;
            if (BIAS) { b0 = bias[c]; b1 = bias[c + 1]; }
            if (OUTK == 1) {
                Ch[(size_t)c * T_LEN + r0]           = __float2half(acc[mf][nf][0] + b0);
                Ch[(size_t)(c + 1) * T_LEN + r0]     = __float2half(acc[mf][nf][1] + b1);
                Ch[(size_t)c * T_LEN + r0 + 8]       = __float2half(acc[mf][nf][2] + b0);
                Ch[(size_t)(c + 1) * T_LEN + r0 + 8] = __float2half(acc[mf][nf][3] + b1);
            } else if (OUTK == 2) {
                *(uint32_t*)&Ch[(size_t)r0 * N + c] =
                    pack_h2(acc[mf][nf][0] + b0, acc[mf][nf][1] + b1);
                *(uint32_t*)&Ch[(size_t)(r0 + 8) * N + c] =
                    pack_h2(acc[mf][nf][2] + b0, acc[mf][nf][3] + b1);
            } else {
                float2 v0 = { acc[mf][nf][0] + b0, acc[mf][nf][1] + b1 };
                float2 v1 = { acc[mf][nf][2] + b0, acc[mf][nf][3] + b1 };
                *(float2*)&C[(size_t)r0 * N + c]       = v0;
                *(float2*)&C[(size_t)(r0 + 8) * N + c] = v1;
            }
        }
    }
}

__global__ __launch_bounds__(256, 2)
void gemm_qkv(const float* __restrict__ b_Q, const float* __restrict__ b_K,
              const float* __restrict__ b_V)
{
    int bx = blockIdx.x, m0 = blockIdx.y * 128;
    if (bx < 32)
        gemm_body<true, 2>(g_Xh, g_WQt, b_Q, nullptr, g_Qh, DMODEL, DMODEL, QDIM, m0, bx * 128, 0, DMODEL);
    else if (bx < 40)
        gemm_body<true, 2>(g_Xh, g_WKt, b_K, nullptr, g_Kh, DMODEL, DMODEL, DMODEL, m0, (bx - 32) * 128, 0, DMODEL);
    else
        gemm_body<true, 1>(g_Xh, g_WVt, b_V, nullptr, g_Vth, DMODEL, DMODEL, DMODEL, m0, (bx - 40) * 128, 0, DMODEL);
}

__global__ __launch_bounds__(256, 2)
void gemm_tc_splitk(float* __restrict__ Cpart, int kPer)
{
    int z = blockIdx.z;
    gemm_body<false, 0>(g_OUTh, g_WOt, nullptr, Cpart + (size_t)z * T_LEN * DMODEL, nullptr,
                        QDIM, QDIM, DMODEL, blockIdx.y * 128, blockIdx.x * 128, z * kPer, kPer);
}

// ---------------------------------------------------------------------------
// RoPE in place on fp16 Q/K + key_self/ATTN_SCALE folding into K.
// ---------------------------------------------------------------------------
__global__ __launch_bounds__(256)
void rope_kernel()
{
    int gw   = blockIdx.x * 8 + (threadIdx.x >> 5);
    int lane = threadIdx.x & 31;
    int slot = gw % (HQ + HK);
    int t    = gw / (HQ + HK);

    bool isK = (slot >= HQ);
    __half* hptr = isK ? (g_Kh + (size_t)t * DMODEL + (slot - HQ) * DH)
                       : (g_Qh + (size_t)t * QDIM + slot * DH);

    __half2 xv = *(__half2*)&hptr[2 * lane];
    float x1 = __low2float(xv);
    float x2 = __high2float(xv);

    // inv = 10000^(-2*lane/64) = 2^(-lane * log2(10000)/32)
    float inv = f_ex2((float)lane * -0.41524100779716735f);
    float fr  = (float)t * inv;
    float s, c;
    sincosf(fr, &s, &c);

    float o1 = x1 * c - x2 * s;
    float o2 = x1 * s + x2 * c;

    if (isK) {
        float nrm = x1 * x1 + x2 * x2;
#pragma unroll
        for (int off = 16; off; off >>= 1)
            nrm += __shfl_xor_sync(0xffffffffu, nrm, off);
        float ks  = fmaxf(nrm, 1e-6f);
        float scl = ATTN_SCALE * rsqrtf(ks);
        o1 *= scl;
        o2 *= scl;
    }
    __syncwarp();   // in-place permutation: all reads complete before writes
    hptr[lane]      = __float2half(o1);
    hptr[lane + 32] = __float2half(o2);
}

// ===========================================================================
// fp16 tensor-core attention (R10 structure) with ldmatrix/stmatrix fragments
// ===========================================================================
#define HPITCH 36
#define HTILE_W (64 * HPITCH)
#define ATTN_SMEM_WORDS (5 * HTILE_W + 128 + 64)
#define ATTN_SMEM_BYTES (ATTN_SMEM_WORDS * 4)

__global__ __launch_bounds__(256, 3)
void attn_tc_kernel(const float* __restrict__ sinks, const float* __restrict__ v_nulls)
{
    extern __shared__ uint32_t smu[];
    uint32_t* KsB[2]  = { smu,               smu + HTILE_W };
    uint32_t* VtsB[2] = { smu + 2 * HTILE_W, smu + 3 * HTILE_W };
    uint32_t* Ws      = smu + 4 * HTILE_W;
    float* RSm = (float*)(smu + 5 * HTILE_W);
    float* Tot = RSm + 128;

    int head = blockIdx.y;
    int qt   = (gridDim.x - 1) - blockIdx.x;   // heavy tiles first
    int kvh  = head & (HK - 1);
    int tid  = threadIdx.x;
    int lane = tid & 31, wid = tid >> 5;
    int wm = wid & 3, wn = wid >> 2;
    int g = lane >> 2, tg = lane & 3;
    int m8 = lane >> 3, rr = lane & 7;
    float sink = sinks[head];

    int crow = tid >> 3, cc = tid & 7;
    uint32_t ksA[2], vtA[2], ksBase[2], vtBase[2];
#pragma unroll
    for (int b = 0; b < 2; ++b) {
        ksBase[b] = smem_u32(KsB[b]);
        vtBase[b] = smem_u32(VtsB[b]);
        ksA[b] = ksBase[b] + (crow * HPITCH + cc * 4) * 4;
        vtA[b] = vtBase[b] + (crow * HPITCH + cc * 4) * 4;
    }
    uint32_t wsBase = smem_u32(Ws);

    // ldmatrix/stmatrix byte offsets
    uint32_t aoffA = ((wm * 16 + (m8 & 1) * 8 + rr) * HPITCH + (m8 >> 1) * 4) * 4;
    uint32_t broffA[2], soffA[2];
#pragma unroll
    for (int p = 0; p < 2; ++p) {
        broffA[p] = ((wn * 32 + (2 * p + (m8 >> 1)) * 8 + rr) * HPITCH + (m8 & 1) * 4) * 4;
        soffA[p]  = ((wm * 16 + (m8 & 1) * 8 + rr) * HPITCH + wn * 16 + (2 * p + (m8 >> 1)) * 4) * 4;
    }

    const __half* kSrc  = g_Kh + (size_t)crow * DMODEL + kvh * DH + cc * 8;
    const __half* vtSrc = g_Vth + (size_t)(kvh * DH + crow) * T_LEN + cc * 8;

#define ISSUE_TILES(kt_, b_)                                                     \
    do {                                                                         \
        cp_async16(ksA[b_],                     kSrc + (size_t)(kt_) * 64 * DMODEL); \
        cp_async16(ksA[b_] + 32 * HPITCH * 4,   kSrc + (size_t)((kt_) * 64 + 32) * DMODEL); \
        cp_async16(vtA[b_],                     vtSrc + (kt_) * 64);             \
        cp_async16(vtA[b_] + 32 * HPITCH * 4,   vtSrc + 32 * T_LEN + (kt_) * 64); \
        CP_COMMIT();                                                             \
    } while (0)

    ISSUE_TILES(0, 0);

    // stage Q through Ws, hoist A-fragments via ldmatrix
    {
        const uint32_t* qsrc = (const uint32_t*)g_Qh;
#pragma unroll
        for (int i = 0; i < 8; ++i) {
            int idx = tid + 256 * i;
            int r = idx >> 5, wc = idx & 31;
            Ws[r * HPITCH + wc] = qsrc[(size_t)(qt * 64 + r) * (QDIM / 2) + head * (DH / 2) + wc];
        }
    }
    __syncthreads();
    int li0 = wm * 16 + g;
    uint32_t afq[4][4];
#pragma unroll
    for (int kk = 0; kk < 4; ++kk)
        ldm_x4(wsBase + aoffA + kk * 32, afq[kk][0], afq[kk][1], afq[kk][2], afq[kk][3]);

    float oacc[4][4];
#pragma unroll
    for (int nf = 0; nf < 4; ++nf)
#pragma unroll
        for (int q = 0; q < 4; ++q) oacc[nf][q] = 0.f;
    float rs0 = 0.f, rs1 = 0.f;
    int gi0 = qt * 64 + li0;

    for (int kt = 0; kt <= qt; ++kt) {
        int b = kt & 1;
        CP_WAIT0();
        __syncthreads();

        if (kt < qt) ISSUE_TILES(kt + 1, b ^ 1);

        // ---- S = Q @ K^T
        float sacc[4][4];
#pragma unroll
        for (int nf = 0; nf < 4; ++nf)
#pragma unroll
            for (int q = 0; q < 4; ++q) sacc[nf][q] = 0.f;

#pragma unroll
        for (int kk = 0; kk < 4; ++kk) {
#pragma unroll
            for (int p = 0; p < 2; ++p) {
                uint32_t b0, b1, b2, b3;
                ldm_x4(ksBase[b] + broffA[p] + kk * 32, b0, b1, b2, b3);
                uint32_t bfa[2] = { b0, b1 }, bfb[2] = { b2, b3 };
                mma_f16(sacc[2 * p],     afq[kk], bfa);
                mma_f16(sacc[2 * p + 1], afq[kk], bfb);
            }
        }

        // ---- activation in registers -> Ws via stmatrix
        bool diag = (kt == qt);
        float wv[4][4];
#pragma unroll
        for (int nf = 0; nf < 4; ++nf) {
            int ljc = wn * 32 + nf * 8 + 2 * tg;
            int gj  = kt * 64 + ljc;
#pragma unroll
            for (int q = 0; q < 4; ++q) {
                float x = fminf(sacc[nf][q], 60.f);
                float t = f_ex2(x * 1.44269504f);
                float u = f_lg2(1.0f + t);
                float ww = 0.69314718f * u * f_rcp(1.0f + f_ex2(-SILU_SCALE * u));
                int gi = gi0 + ((q >> 1) << 3);
                int gjj = gj + (q & 1);
                if ((diag && gjj > gi) || ww < sink) ww = 0.f;
                wv[nf][q] = ww;
            }
            rs0 += wv[nf][0] + wv[nf][1];
            rs1 += wv[nf][2] + wv[nf][3];
        }
        stm_x4(wsBase + soffA[0],
               pack_h2(wv[0][0], wv[0][1]), pack_h2(wv[0][2], wv[0][3]),
               pack_h2(wv[1][0], wv[1][1]), pack_h2(wv[1][2], wv[1][3]));
        stm_x4(wsBase + soffA[1],
               pack_h2(wv[2][0], wv[2][1]), pack_h2(wv[2][2], wv[2][3]),
               pack_h2(wv[3][0], wv[3][1]), pack_h2(wv[3][2], wv[3][3]));
        __syncthreads();

        // ---- O += W @ V
#pragma unroll
        for (int kk = 0; kk < 4; ++kk) {
            uint32_t af[4];
            ldm_x4(wsBase + aoffA + kk * 32, af[0], af[1], af[2], af[3]);
#pragma unroll
            for (int p = 0; p < 2; ++p) {
                uint32_t b0, b1, b2, b3;
                ldm_x4(vtBase[b] + broffA[p] + kk * 32, b0, b1, b2, b3);
                uint32_t bfa[2] = { b0, b1 }, bfb[2] = { b2, b3 };
                mma_f16(oacc[2 * p],     af, bfa);
                mma_f16(oacc[2 * p + 1], af, bfb);
            }
        }
    }
#undef ISSUE_TILES

    __syncthreads();
    rs0 += __shfl_xor_sync(0xffffffffu, rs0, 1);
    rs0 += __shfl_xor_sync(0xffffffffu, rs0, 2);
    rs1 += __shfl_xor_sync(0xffffffffu, rs1, 1);
    rs1 += __shfl_xor_sync(0xffffffffu, rs1, 2);
    if (tg == 0) {
        RSm[wid * 16 + g]     = rs0;
        RSm[wid * 16 + 8 + g] = rs1;
    }
    __syncthreads();
    if (tid < 64)
        Tot[tid] = RSm[(tid >> 4) * 16 + (tid & 15)]
                 + RSm[((tid >> 4) + 4) * 16 + (tid & 15)] + sink + 1e-6f;
    __syncthreads();

    float invT0 = 1.0f / Tot[li0];
    float invT1 = 1.0f / Tot[li0 + 8];
#pragma unroll
    for (int nf = 0; nf < 4; ++nf) {
        int dloc = wn * 32 + nf * 8 + 2 * tg;
        float vn0 = v_nulls[head * DH + dloc];
        float vn1 = v_nulls[head * DH + dloc + 1];
        uint32_t o0 = pack_h2((oacc[nf][0] + sink * vn0) * invT0,
                              (oacc[nf][1] + sink * vn1) * invT0);
        uint32_t o1 = pack_h2((oacc[nf][2] + sink * vn0) * invT1,
                              (oacc[nf][3] + sink * vn1) * invT1);
        *(uint32_t*)&g_OUTh[(size_t)(qt * 64 + li0) * QDIM + head * DH + dloc]     = o0;
        *(uint32_t*)&g_OUTh[(size_t)(qt * 64 + li0 + 8) * QDIM + head * DH + dloc] = o1;
    }
}

// ---------------------------------------------------------------------------
// Final reduce: Y = 0.25 * (sum of 4 K-split partials + sum_br bias)
// ---------------------------------------------------------------------------
__global__ __launch_bounds__(256)
void reduce_out_kernel(const float* __restrict__ part, const float* __restrict__ wob,
                       float* __restrict__ out)
{
    int idx = blockIdx.x * 256 + threadIdx.x;
    int d = idx & (DMODEL - 1);
    float s = part[idx] + part[idx + 1048576] + part[idx + 2097152] + part[idx + 3145728];
    float b = wob[d] + wob[DMODEL + d] + wob[2 * DMODEL + d] + wob[3 * DMODEL + d];
    out[idx] = 0.25f * (s + b);
}

// ---------------------------------------------------------------------------
extern "C" void kernel_launch(void* const* d_in, const int* in_sizes, int n_in,
                              void* d_out, int out_size)
{
    const float* X        = (const float*)d_in[0];
    const float* W_Q      = (const float*)d_in[1];
    const float* b_Q      = (const float*)d_in[2];
    const float* W_K      = (const float*)d_in[3];
    const float* b_K      = (const float*)d_in[4];
    const float* W_V      = (const float*)d_in[5];
    const float* b_V      = (const float*)d_in[6];
    const float* sinks    = (const float*)d_in[7];
    const float* v_nulls  = (const float*)d_in[8];
    const float* W_O      = (const float*)d_in[9];
    const float* W_O_bias = (const float*)d_in[10];
    float* out = (float*)d_out;

    float* PARTp;
    cudaGetSymbolAddress((void**)&PARTp, g_part);

    cudaFuncSetAttribute(gemm_qkv, cudaFuncAttributeMaxDynamicSharedMemorySize, GEMM_SMEM_BYTES);
    cudaFuncSetAttribute(gemm_tc_splitk, cudaFuncAttributeMaxDynamicSharedMemorySize, GEMM_SMEM_BYTES);
    cudaFuncSetAttribute(attn_tc_kernel, cudaFuncAttributeMaxDynamicSharedMemorySize, ATTN_SMEM_BYTES);

    // fp16 conversion: X elementwise (z=0), weights transposed (z=1..4)
    convert_ops<<<dim3(4096, 5), 256>>>(X, W_Q, W_K, W_V, W_O);
    // fused Q/K/V projections -> fp16 Q/K rows + fp16 V^T
    gemm_qkv<<<dim3(48, 8, 1), 256, GEMM_SMEM_BYTES>>>(b_Q, b_K, b_V);
    // RoPE in place on fp16 Q/K (+ key_self folding)
    rope_kernel<<<10240, 256>>>();
    // fp16 tensor-core attention
    attn_tc_kernel<<<dim3(16, 64), 256, ATTN_SMEM_BYTES>>>(sinks, v_nulls);
    // output projection, split-K=4
    gemm_tc_splitk<<<dim3(8, 8, 4), 256, GEMM_SMEM_BYTES>>>(PARTp, 1024);
    reduce_out_kernel<<<4096, 256>>>(PARTp, W_O_bias, out);
}